// round 1
// baseline (speedup 1.0000x reference)
#include <cuda_runtime.h>
#include <math.h>

#define Bb  2
#define Tt  2048
#define Cc  2048
#define Hh  16
#define KVh 4
#define Dd  128
#define REP 4   // Hh / KVh

// ---------------- scratch (device globals; no allocation allowed) ----------
__device__ float g_cos[Tt * 64];
__device__ float g_sin[Tt * 64];
__device__ float g_q[(size_t)Bb * Hh  * Tt * Dd];   // (b,h,t,d)
__device__ float g_k[(size_t)Bb * KVh * Tt * Dd];   // (b,kv,t,d)
__device__ float g_v[(size_t)Bb * KVh * Tt * Dd];
__device__ float g_att[(size_t)Bb * Tt * Cc];       // (b*t, h*d) row-major

// ---------------- RoPE tables ----------------------------------------------
__global__ void rope_tables_kernel() {
    int idx = blockIdx.x * blockDim.x + threadIdx.x;
    if (idx >= Tt * 64) return;
    int t = idx / 64, i = idx % 64;
    double inv = pow(10000.0, -(double)(2 * i) / 128.0);
    double ang = (double)t * inv;
    g_cos[idx] = (float)cos(ang);
    g_sin[idx] = (float)sin(ang);
}

// ---------------- RoPE apply (in place, layout (bh, t, d)) ------------------
__global__ void rope_apply_kernel(float* buf, int nheads) {
    int idx = blockIdx.x * blockDim.x + threadIdx.x;
    int total = Bb * nheads * Tt * 64;
    if (idx >= total) return;
    int d  = idx & 63;
    int t  = (idx >> 6) & (Tt - 1);
    int bh = idx / (64 * Tt);
    float c = g_cos[t * 64 + d];
    float s = g_sin[t * 64 + d];
    float* p = buf + ((size_t)bh * Tt + t) * Dd;
    float x1 = p[d], x2 = p[d + 64];
    p[d]      = x1 * c - x2 * s;
    p[d + 64] = x2 * c + x1 * s;
}

// ---------------- Generic NT GEMM: C = A(MxK) * B(NxK)^T --------------------
// 128x128 tile, 256 threads, 8x8 micro tile, BK=16.
// MODE 0: plain row-major C[M][N].
// MODE 1: headed output: row=(b,t), col=(h,d) -> C[((b*nh+h)*T + t)*D + d]
template <int MODE>
__global__ void gemm_nt_kernel(const float* __restrict__ A,
                               const float* __restrict__ Bm,
                               float* __restrict__ Cout,
                               int M, int N, int K, int nh) {
    __shared__ float As[16][132];
    __shared__ float Bs[16][132];

    const int m0 = blockIdx.y * 128;
    const int n0 = blockIdx.x * 128;
    const int tid = threadIdx.x;
    const int tx = tid & 15;      // 0..15
    const int ty = tid >> 4;      // 0..15

    float acc[8][8];
#pragma unroll
    for (int i = 0; i < 8; i++)
#pragma unroll
        for (int j = 0; j < 8; j++) acc[i][j] = 0.f;

    const int lr  = tid >> 1;     // 0..127 : row within tile
    const int seg = tid & 1;      // k-half
    const float* aptr = A  + (size_t)(m0 + lr) * K + seg * 8;
    const float* bptr = Bm + (size_t)(n0 + lr) * K + seg * 8;

    for (int kk = 0; kk < K; kk += 16) {
        float4 av0 = *(const float4*)(aptr + kk);
        float4 av1 = *(const float4*)(aptr + kk + 4);
        float4 bv0 = *(const float4*)(bptr + kk);
        float4 bv1 = *(const float4*)(bptr + kk + 4);
        const int kb = seg * 8;
        As[kb + 0][lr] = av0.x; As[kb + 1][lr] = av0.y;
        As[kb + 2][lr] = av0.z; As[kb + 3][lr] = av0.w;
        As[kb + 4][lr] = av1.x; As[kb + 5][lr] = av1.y;
        As[kb + 6][lr] = av1.z; As[kb + 7][lr] = av1.w;
        Bs[kb + 0][lr] = bv0.x; Bs[kb + 1][lr] = bv0.y;
        Bs[kb + 2][lr] = bv0.z; Bs[kb + 3][lr] = bv0.w;
        Bs[kb + 4][lr] = bv1.x; Bs[kb + 5][lr] = bv1.y;
        Bs[kb + 6][lr] = bv1.z; Bs[kb + 7][lr] = bv1.w;
        __syncthreads();

#pragma unroll
        for (int k = 0; k < 16; k++) {
            float a[8], b[8];
#pragma unroll
            for (int i = 0; i < 8; i++) a[i] = As[k][ty + 16 * i];
#pragma unroll
            for (int j = 0; j < 8; j++) b[j] = Bs[k][tx + 16 * j];
#pragma unroll
            for (int i = 0; i < 8; i++)
#pragma unroll
                for (int j = 0; j < 8; j++) acc[i][j] += a[i] * b[j];
        }
        __syncthreads();
    }

#pragma unroll
    for (int i = 0; i < 8; i++) {
        int row = m0 + ty + 16 * i;
#pragma unroll
        for (int j = 0; j < 8; j++) {
            int col = n0 + tx + 16 * j;
            if (MODE == 0) {
                Cout[(size_t)row * N + col] = acc[i][j];
            } else {
                int b = row / Tt, t = row & (Tt - 1);
                int h = col >> 7, d = col & 127;
                Cout[(((size_t)b * nh + h) * Tt + t) * Dd + d] = acc[i][j];
            }
        }
    }
}

// ---------------- Flash attention (causal, GQA) -----------------------------
// grid (T/64, H, B), 128 threads. 64 q-rows per block, D=128.
#define QS_STR 132
#define PS_STR 65

__global__ void flash_attn_kernel() {
    extern __shared__ float sm[];
    float* Qs  = sm;                        // 64*132
    float* Ks  = Qs + 64 * QS_STR;          // 64*132
    float* Vs  = Ks + 64 * QS_STR;          // 64*132
    float* Ps  = Vs + 64 * QS_STR;          // 64*65
    float* m_s = Ps + 64 * PS_STR;          // 64
    float* l_s = m_s + 64;                  // 64
    float* al_s = l_s + 64;                 // 64

    const int it = blockIdx.x;
    const int h  = blockIdx.y;
    const int b  = blockIdx.z;
    const int kvh = h / REP;

    const float* qp = g_q + (((size_t)b * Hh  + h)   * Tt + it * 64) * Dd;
    const float* kp = g_k + (((size_t)b * KVh + kvh) * Tt) * Dd;
    const float* vp = g_v + (((size_t)b * KVh + kvh) * Tt) * Dd;

    const int tid = threadIdx.x;
    const int tx = tid & 7;       // 0..7
    const int ty = tid >> 3;      // 0..15

    // load Q tile (64x128 floats = 2048 float4)
    for (int u = tid; u < 64 * 32; u += 128) {
        int r = u >> 5, c4 = u & 31;
        *(float4*)(Qs + r * QS_STR + c4 * 4) = *(const float4*)(qp + r * 128 + c4 * 4);
    }
    if (tid < 64) { m_s[tid] = -INFINITY; l_s[tid] = 0.f; }

    float Oacc[4][16];
#pragma unroll
    for (int i = 0; i < 4; i++)
#pragma unroll
        for (int d = 0; d < 16; d++) Oacc[i][d] = 0.f;

    __syncthreads();
    const float scale = 0.08838834764831845f; // 1/sqrt(128)

    for (int jt = 0; jt <= it; jt++) {
        // load K, V tiles
        for (int u = tid; u < 64 * 32; u += 128) {
            int r = u >> 5, c4 = u & 31;
            *(float4*)(Ks + r * QS_STR + c4 * 4) =
                *(const float4*)(kp + (size_t)(jt * 64 + r) * 128 + c4 * 4);
            *(float4*)(Vs + r * QS_STR + c4 * 4) =
                *(const float4*)(vp + (size_t)(jt * 64 + r) * 128 + c4 * 4);
        }
        __syncthreads();

        // S = Q K^T  (rows ty+16i, cols tx+8j)
        float s[4][8];
#pragma unroll
        for (int i = 0; i < 4; i++)
#pragma unroll
            for (int j = 0; j < 8; j++) s[i][j] = 0.f;

#pragma unroll 4
        for (int k = 0; k < 128; k++) {
            float a[4], bb[8];
#pragma unroll
            for (int i = 0; i < 4; i++) a[i] = Qs[(ty + 16 * i) * QS_STR + k];
#pragma unroll
            for (int j = 0; j < 8; j++) bb[j] = Ks[(tx + 8 * j) * QS_STR + k];
#pragma unroll
            for (int i = 0; i < 4; i++)
#pragma unroll
                for (int j = 0; j < 8; j++) s[i][j] += a[i] * bb[j];
        }

        const bool diag = (jt == it);
#pragma unroll
        for (int i = 0; i < 4; i++) {
            int r = ty + 16 * i;
#pragma unroll
            for (int j = 0; j < 8; j++) {
                float sv = s[i][j] * scale;
                if (diag && (tx + 8 * j) > r) sv = -INFINITY;
                s[i][j] = sv;
            }
        }

        // online softmax per row (8 lanes share a row via tx)
#pragma unroll
        for (int i = 0; i < 4; i++) {
            int row = ty + 16 * i;
            float mx = s[i][0];
#pragma unroll
            for (int j = 1; j < 8; j++) mx = fmaxf(mx, s[i][j]);
            mx = fmaxf(mx, __shfl_xor_sync(0xffffffffu, mx, 1));
            mx = fmaxf(mx, __shfl_xor_sync(0xffffffffu, mx, 2));
            mx = fmaxf(mx, __shfl_xor_sync(0xffffffffu, mx, 4));
            float mold = m_s[row];
            float mnew = fmaxf(mold, mx);
            float lsum = 0.f;
#pragma unroll
            for (int j = 0; j < 8; j++) {
                float p = __expf(s[i][j] - mnew);
                Ps[row * PS_STR + tx + 8 * j] = p;
                lsum += p;
            }
            lsum += __shfl_xor_sync(0xffffffffu, lsum, 1);
            lsum += __shfl_xor_sync(0xffffffffu, lsum, 2);
            lsum += __shfl_xor_sync(0xffffffffu, lsum, 4);
            if (tx == 0) {
                float alpha = __expf(mold - mnew);
                al_s[row] = alpha;
                l_s[row]  = l_s[row] * alpha + lsum;
                m_s[row]  = mnew;
            }
        }
        __syncthreads();

        // O = O*alpha + P @ V   (rows ty+16i, d-cols tx*16..tx*16+15)
        float alpha[4];
#pragma unroll
        for (int i = 0; i < 4; i++) alpha[i] = al_s[ty + 16 * i];
#pragma unroll
        for (int i = 0; i < 4; i++)
#pragma unroll
            for (int d = 0; d < 16; d++) Oacc[i][d] *= alpha[i];

        const int d0 = tx * 16;
#pragma unroll 2
        for (int j = 0; j < 64; j++) {
            float4 v0 = *(const float4*)(Vs + j * QS_STR + d0);
            float4 v1 = *(const float4*)(Vs + j * QS_STR + d0 + 4);
            float4 v2 = *(const float4*)(Vs + j * QS_STR + d0 + 8);
            float4 v3 = *(const float4*)(Vs + j * QS_STR + d0 + 12);
            float p[4];
#pragma unroll
            for (int i = 0; i < 4; i++) p[i] = Ps[(ty + 16 * i) * PS_STR + j];
#pragma unroll
            for (int i = 0; i < 4; i++) {
                Oacc[i][0]  += p[i] * v0.x;  Oacc[i][1]  += p[i] * v0.y;
                Oacc[i][2]  += p[i] * v0.z;  Oacc[i][3]  += p[i] * v0.w;
                Oacc[i][4]  += p[i] * v1.x;  Oacc[i][5]  += p[i] * v1.y;
                Oacc[i][6]  += p[i] * v1.z;  Oacc[i][7]  += p[i] * v1.w;
                Oacc[i][8]  += p[i] * v2.x;  Oacc[i][9]  += p[i] * v2.y;
                Oacc[i][10] += p[i] * v2.z;  Oacc[i][11] += p[i] * v2.w;
                Oacc[i][12] += p[i] * v3.x;  Oacc[i][13] += p[i] * v3.y;
                Oacc[i][14] += p[i] * v3.z;  Oacc[i][15] += p[i] * v3.w;
            }
        }
        __syncthreads();
    }

    // finalize: divide by l, write (b*t, h*d) layout
#pragma unroll
    for (int i = 0; i < 4; i++) {
        int r = ty + 16 * i;
        float inv = 1.f / l_s[r];
        int t = it * 64 + r;
        float* op = g_att + ((size_t)b * Tt + t) * Cc + h * Dd + tx * 16;
        float4 w;
#pragma unroll
        for (int g = 0; g < 4; g++) {
            w.x = Oacc[i][4 * g + 0] * inv;
            w.y = Oacc[i][4 * g + 1] * inv;
            w.z = Oacc[i][4 * g + 2] * inv;
            w.w = Oacc[i][4 * g + 3] * inv;
            *(float4*)(op + 4 * g) = w;
        }
    }
}

// ---------------- launch ----------------------------------------------------
extern "C" void kernel_launch(void* const* d_in, const int* in_sizes, int n_in,
                              void* d_out, int out_size) {
    const float* x  = (const float*)d_in[0];
    const float* Wq = (const float*)d_in[1];
    const float* Wk = (const float*)d_in[2];
    const float* Wv = (const float*)d_in[3];
    const float* Wo = (const float*)d_in[4];
    float* out = (float*)d_out;

    float *pq, *pk, *pv, *patt;
    cudaGetSymbolAddress((void**)&pq,   g_q);
    cudaGetSymbolAddress((void**)&pk,   g_k);
    cudaGetSymbolAddress((void**)&pv,   g_v);
    cudaGetSymbolAddress((void**)&patt, g_att);

    const int M = Bb * Tt;        // 4096

    // 1. RoPE tables
    rope_tables_kernel<<<(Tt * 64 + 255) / 256, 256>>>();

    // 2. projections
    gemm_nt_kernel<1><<<dim3(Cc / 128, M / 128), 256>>>(x, Wq, pq, M, Cc, Cc, Hh);
    gemm_nt_kernel<1><<<dim3((KVh * Dd) / 128, M / 128), 256>>>(x, Wk, pk, M, KVh * Dd, Cc, KVh);
    gemm_nt_kernel<1><<<dim3((KVh * Dd) / 128, M / 128), 256>>>(x, Wv, pv, M, KVh * Dd, Cc, KVh);

    // 3. RoPE on q and k
    rope_apply_kernel<<<(Bb * Hh * Tt * 64 + 255) / 256, 256>>>(pq, Hh);
    rope_apply_kernel<<<(Bb * KVh * Tt * 64 + 255) / 256, 256>>>(pk, KVh);

    // 4. flash attention
    const int smem = (3 * 64 * QS_STR + 64 * PS_STR + 3 * 64) * (int)sizeof(float);
    cudaFuncSetAttribute(flash_attn_kernel,
                         cudaFuncAttributeMaxDynamicSharedMemorySize, smem);
    flash_attn_kernel<<<dim3(Tt / 64, Hh, Bb), 128, smem>>>();

    // 5. output projection
    gemm_nt_kernel<0><<<dim3(Cc / 128, M / 128), 256>>>(patt, Wo, out, M, Cc, Cc, 0);
}

// round 3
// speedup vs baseline: 1.5813x; 1.5813x over previous
#include <cuda_runtime.h>
#include <cuda_bf16.h>
#include <math.h>
#include <stdint.h>

#define Bb  2
#define Tt  2048
#define Cc  2048
#define Hh  16
#define KVh 4
#define Dd  128
#define REP 4   // Hh / KVh

// ---------------- scratch (device globals; no allocation allowed) ----------
__device__ float g_cos[Tt * 64];
__device__ float g_sin[Tt * 64];
__device__ float g_q[(size_t)Bb * Hh  * Tt * Dd];   // (b,h,t,d)
__device__ float g_k[(size_t)Bb * KVh * Tt * Dd];   // (b,kv,t,d)
__device__ float g_v[(size_t)Bb * KVh * Tt * Dd];
__device__ float g_att[(size_t)Bb * Tt * Cc];       // (b*t, h*d) row-major

// ---------------- RoPE tables ----------------------------------------------
__global__ void rope_tables_kernel() {
    int idx = blockIdx.x * blockDim.x + threadIdx.x;
    if (idx >= Tt * 64) return;
    int t = idx / 64, i = idx % 64;
    double inv = pow(10000.0, -(double)(2 * i) / 128.0);
    double ang = (double)t * inv;
    g_cos[idx] = (float)cos(ang);
    g_sin[idx] = (float)sin(ang);
}

// ---------------- RoPE apply (in place, layout (bh, t, d)) ------------------
__global__ void rope_apply_kernel(float* buf, int nheads) {
    int idx = blockIdx.x * blockDim.x + threadIdx.x;
    int total = Bb * nheads * Tt * 64;
    if (idx >= total) return;
    int d  = idx & 63;
    int t  = (idx >> 6) & (Tt - 1);
    int bh = idx / (64 * Tt);
    float c = g_cos[t * 64 + d];
    float s = g_sin[t * 64 + d];
    float* p = buf + ((size_t)bh * Tt + t) * Dd;
    float x1 = p[d], x2 = p[d + 64];
    p[d]      = x1 * c - x2 * s;
    p[d + 64] = x2 * c + x1 * s;
}

// ======================= HMMA helpers ======================================
__device__ __forceinline__ void mma16816(float* c, const uint32_t* a, const uint32_t* b) {
    asm volatile(
        "mma.sync.aligned.m16n8k16.row.col.f32.bf16.bf16.f32 "
        "{%0,%1,%2,%3}, {%4,%5,%6,%7}, {%8,%9}, {%0,%1,%2,%3};"
        : "+f"(c[0]), "+f"(c[1]), "+f"(c[2]), "+f"(c[3])
        : "r"(a[0]), "r"(a[1]), "r"(a[2]), "r"(a[3]), "r"(b[0]), "r"(b[1]));
}

__device__ __forceinline__ void ldsm_x4(uint32_t& r0, uint32_t& r1, uint32_t& r2,
                                        uint32_t& r3, uint32_t addr) {
    asm volatile("ldmatrix.sync.aligned.m8n8.x4.shared.b16 {%0,%1,%2,%3}, [%4];"
                 : "=r"(r0), "=r"(r1), "=r"(r2), "=r"(r3) : "r"(addr));
}
__device__ __forceinline__ void ldsm_x2(uint32_t& r0, uint32_t& r1, uint32_t addr) {
    asm volatile("ldmatrix.sync.aligned.m8n8.x2.shared.b16 {%0,%1}, [%2];"
                 : "=r"(r0), "=r"(r1) : "r"(addr));
}

__device__ __forceinline__ uint32_t smem_u32_(const void* p) {
    uint32_t a;
    asm("{ .reg .u64 t; cvta.to.shared.u64 t, %1; cvt.u32.u64 %0, t; }"
        : "=r"(a) : "l"(p));
    return a;
}

// pack two floats to bf16x2 (lo -> low half, hi -> high half)
__device__ __forceinline__ uint32_t pack_bf16x2(float lo, float hi) {
    uint32_t r;
    asm("cvt.rn.bf16x2.f32 %0, %1, %2;" : "=r"(r) : "f"(hi), "f"(lo));
    return r;
}

// ======================= HMMA split-bf16 GEMM ===============================
// C = A(MxK) * B(NxK)^T, fp32 in/out.
// 3-pass: C ~= Ahi Bhi + Ahi Blo + Alo Bhi, error ~2^-16 per term.
// CTA tile 128x128, 8 warps 2x4, warp tile 64x32, BK=32, double-buffered smem.
// MODE 0: C[row*N+col]. MODE 1: row=(b,t), col=(h,d) -> [((b*nh+h)*T+t)*128+d]

#define BK      32
#define LDH     40                 // smem stride in halves (32 + 8 pad)
#define TILE_B  (128 * LDH * 2)    // bytes per tile matrix = 10240
#define STAGE_B (4 * TILE_B)       // Ahi, Alo, Bhi, Blo   = 40960

template <int MODE>
__global__ void __launch_bounds__(256, 1)
gemm_hmma_kernel(const float* __restrict__ A, const float* __restrict__ Bm,
                 float* __restrict__ Cout, int M, int N, int K, int nh)
{
    extern __shared__ char smem[];
    const uint32_t sb = smem_u32_(smem);

    const int tid  = threadIdx.x;
    const int wid  = tid >> 5;
    const int lane = tid & 31;
    const int wr   = wid >> 2;          // 0..1 (64-row band)
    const int wc   = wid & 3;           // 0..3 (32-col band)
    const int m0   = blockIdx.y * 128;
    const int n0   = blockIdx.x * 128;

    // staging: thread -> row tid>>1, k-seg (tid&1)*16
    const int srow = tid >> 1;
    const int sseg = tid & 1;
    const float* aptr = A  + (size_t)(m0 + srow) * K + sseg * 16;
    const float* bptr = Bm + (size_t)(n0 + srow) * K + sseg * 16;

    float acc[4][4][4];
#pragma unroll
    for (int i = 0; i < 4; i++)
#pragma unroll
        for (int j = 0; j < 4; j++)
#pragma unroll
            for (int q = 0; q < 4; q++) acc[i][j][q] = 0.f;

    const int NC = K / BK;

    // ---- staging store helper (lambda-free, macro-ish via function) -------
    auto store_chunk = [&](const float4* ga, const float4* gb, int stage) {
        // convert 16 floats of A and B into hi/lo bf16 and store
        uint32_t hA[8], lA[8], hB[8], lB[8];
#pragma unroll
        for (int g = 0; g < 4; g++) {
            float4 v = ga[g];
            __nv_bfloat16 e0 = __float2bfloat16(v.x);
            __nv_bfloat16 e1 = __float2bfloat16(v.y);
            __nv_bfloat16 e2 = __float2bfloat16(v.z);
            __nv_bfloat16 e3 = __float2bfloat16(v.w);
            hA[2*g]   = ((uint32_t)__bfloat16_as_ushort(e1) << 16) | __bfloat16_as_ushort(e0);
            hA[2*g+1] = ((uint32_t)__bfloat16_as_ushort(e3) << 16) | __bfloat16_as_ushort(e2);
            lA[2*g]   = pack_bf16x2(v.x - __bfloat162float(e0), v.y - __bfloat162float(e1));
            lA[2*g+1] = pack_bf16x2(v.z - __bfloat162float(e2), v.w - __bfloat162float(e3));
        }
#pragma unroll
        for (int g = 0; g < 4; g++) {
            float4 v = gb[g];
            __nv_bfloat16 e0 = __float2bfloat16(v.x);
            __nv_bfloat16 e1 = __float2bfloat16(v.y);
            __nv_bfloat16 e2 = __float2bfloat16(v.z);
            __nv_bfloat16 e3 = __float2bfloat16(v.w);
            hB[2*g]   = ((uint32_t)__bfloat16_as_ushort(e1) << 16) | __bfloat16_as_ushort(e0);
            hB[2*g+1] = ((uint32_t)__bfloat16_as_ushort(e3) << 16) | __bfloat16_as_ushort(e2);
            lB[2*g]   = pack_bf16x2(v.x - __bfloat162float(e0), v.y - __bfloat162float(e1));
            lB[2*g+1] = pack_bf16x2(v.z - __bfloat162float(e2), v.w - __bfloat162float(e3));
        }
        char* st = smem + stage * STAGE_B;
        uint32_t off = (uint32_t)(srow * LDH + sseg * 16) * 2;  // bytes
        *(uint4*)(st + 0*TILE_B + off)      = *(uint4*)&hA[0];
        *(uint4*)(st + 0*TILE_B + off + 16) = *(uint4*)&hA[4];
        *(uint4*)(st + 1*TILE_B + off)      = *(uint4*)&lA[0];
        *(uint4*)(st + 1*TILE_B + off + 16) = *(uint4*)&lA[4];
        *(uint4*)(st + 2*TILE_B + off)      = *(uint4*)&hB[0];
        *(uint4*)(st + 2*TILE_B + off + 16) = *(uint4*)&hB[4];
        *(uint4*)(st + 3*TILE_B + off)      = *(uint4*)&lB[0];
        *(uint4*)(st + 3*TILE_B + off + 16) = *(uint4*)&lB[4];
    };

    // preload chunk 0
    float4 ga[4], gb[4];
#pragma unroll
    for (int g = 0; g < 4; g++) {
        ga[g] = *(const float4*)(aptr + g * 4);
        gb[g] = *(const float4*)(bptr + g * 4);
    }
    store_chunk(ga, gb, 0);
    __syncthreads();

    // ldmatrix lane addressing (byte offsets within a tile matrix)
    const uint32_t a_row = wr * 64 + (lane & 15);
    const uint32_t a_kh  = (lane >> 4) * 8;
    const uint32_t b_row = wc * 32 + (lane & 7);
    const uint32_t b_kh  = ((lane >> 3) & 1) * 8;

    for (int i = 0; i < NC; i++) {
        const int s = i & 1;
        if (i + 1 < NC) {
            const int kk = (i + 1) * BK;
#pragma unroll
            for (int g = 0; g < 4; g++) {
                ga[g] = *(const float4*)(aptr + kk + g * 4);
                gb[g] = *(const float4*)(bptr + kk + g * 4);
            }
        }

        const uint32_t stb = sb + s * STAGE_B;
#pragma unroll
        for (int kstep = 0; kstep < 2; kstep++) {
            const uint32_t kof = kstep * 16;
            uint32_t ahi[4][4], alo[4][4], bhi[4][2], blo[4][2];
#pragma unroll
            for (int mt = 0; mt < 4; mt++) {
                uint32_t ad = stb + ((a_row + mt * 16) * LDH + kof + a_kh) * 2;
                ldsm_x4(ahi[mt][0], ahi[mt][1], ahi[mt][2], ahi[mt][3], ad + 0 * TILE_B);
                ldsm_x4(alo[mt][0], alo[mt][1], alo[mt][2], alo[mt][3], ad + 1 * TILE_B);
            }
#pragma unroll
            for (int nt = 0; nt < 4; nt++) {
                uint32_t bd = stb + ((b_row + nt * 8) * LDH + kof + b_kh) * 2;
                ldsm_x2(bhi[nt][0], bhi[nt][1], bd + 2 * TILE_B);
                ldsm_x2(blo[nt][0], blo[nt][1], bd + 3 * TILE_B);
            }
#pragma unroll
            for (int mt = 0; mt < 4; mt++)
#pragma unroll
                for (int nt = 0; nt < 4; nt++) {
                    mma16816(acc[mt][nt], ahi[mt], bhi[nt]);
                    mma16816(acc[mt][nt], ahi[mt], blo[nt]);
                    mma16816(acc[mt][nt], alo[mt], bhi[nt]);
                }
        }
        __syncthreads();
        if (i + 1 < NC) {
            store_chunk(ga, gb, s ^ 1);
            __syncthreads();
        }
    }

    // epilogue
#pragma unroll
    for (int mt = 0; mt < 4; mt++) {
        const int r0 = m0 + wr * 64 + mt * 16 + (lane >> 2);
        const int r1 = r0 + 8;
#pragma unroll
        for (int nt = 0; nt < 4; nt++) {
            const int c = n0 + wc * 32 + nt * 8 + (lane & 3) * 2;
            if (MODE == 0) {
                *(float2*)(Cout + (size_t)r0 * N + c) = make_float2(acc[mt][nt][0], acc[mt][nt][1]);
                *(float2*)(Cout + (size_t)r1 * N + c) = make_float2(acc[mt][nt][2], acc[mt][nt][3]);
            } else {
                const int h = c >> 7, d = c & 127;
                const int b0_ = r0 / Tt, t0_ = r0 & (Tt - 1);
                const int b1_ = r1 / Tt, t1_ = r1 & (Tt - 1);
                *(float2*)(Cout + (((size_t)b0_ * nh + h) * Tt + t0_) * Dd + d) =
                    make_float2(acc[mt][nt][0], acc[mt][nt][1]);
                *(float2*)(Cout + (((size_t)b1_ * nh + h) * Tt + t1_) * Dd + d) =
                    make_float2(acc[mt][nt][2], acc[mt][nt][3]);
            }
        }
    }
}

// ---------------- Flash attention (causal, GQA, fp32) -----------------------
#define QS_STR 132
#define PS_STR 65

__global__ void flash_attn_kernel() {
    extern __shared__ float smf[];
    float* Qs  = smf;
    float* Ks  = Qs + 64 * QS_STR;
    float* Vs  = Ks + 64 * QS_STR;
    float* Ps  = Vs + 64 * QS_STR;
    float* m_s = Ps + 64 * PS_STR;
    float* l_s = m_s + 64;
    float* al_s = l_s + 64;

    const int it = blockIdx.x;
    const int h  = blockIdx.y;
    const int b  = blockIdx.z;
    const int kvh = h / REP;

    const float* qp = g_q + (((size_t)b * Hh  + h)   * Tt + it * 64) * Dd;
    const float* kp = g_k + (((size_t)b * KVh + kvh) * Tt) * Dd;
    const float* vp = g_v + (((size_t)b * KVh + kvh) * Tt) * Dd;

    const int tid = threadIdx.x;
    const int tx = tid & 7;
    const int ty = tid >> 3;

    for (int u = tid; u < 64 * 32; u += 128) {
        int r = u >> 5, c4 = u & 31;
        *(float4*)(Qs + r * QS_STR + c4 * 4) = *(const float4*)(qp + r * 128 + c4 * 4);
    }
    if (tid < 64) { m_s[tid] = -INFINITY; l_s[tid] = 0.f; }

    float Oacc[4][16];
#pragma unroll
    for (int i = 0; i < 4; i++)
#pragma unroll
        for (int d = 0; d < 16; d++) Oacc[i][d] = 0.f;

    __syncthreads();
    const float scale = 0.08838834764831845f;

    for (int jt = 0; jt <= it; jt++) {
        for (int u = tid; u < 64 * 32; u += 128) {
            int r = u >> 5, c4 = u & 31;
            *(float4*)(Ks + r * QS_STR + c4 * 4) =
                *(const float4*)(kp + (size_t)(jt * 64 + r) * 128 + c4 * 4);
            *(float4*)(Vs + r * QS_STR + c4 * 4) =
                *(const float4*)(vp + (size_t)(jt * 64 + r) * 128 + c4 * 4);
        }
        __syncthreads();

        float s[4][8];
#pragma unroll
        for (int i = 0; i < 4; i++)
#pragma unroll
            for (int j = 0; j < 8; j++) s[i][j] = 0.f;

#pragma unroll 4
        for (int k = 0; k < 128; k++) {
            float a[4], bb[8];
#pragma unroll
            for (int i = 0; i < 4; i++) a[i] = Qs[(ty + 16 * i) * QS_STR + k];
#pragma unroll
            for (int j = 0; j < 8; j++) bb[j] = Ks[(tx + 8 * j) * QS_STR + k];
#pragma unroll
            for (int i = 0; i < 4; i++)
#pragma unroll
                for (int j = 0; j < 8; j++) s[i][j] += a[i] * bb[j];
        }

        const bool diag = (jt == it);
#pragma unroll
        for (int i = 0; i < 4; i++) {
            int r = ty + 16 * i;
#pragma unroll
            for (int j = 0; j < 8; j++) {
                float sv = s[i][j] * scale;
                if (diag && (tx + 8 * j) > r) sv = -INFINITY;
                s[i][j] = sv;
            }
        }

#pragma unroll
        for (int i = 0; i < 4; i++) {
            int row = ty + 16 * i;
            float mx = s[i][0];
#pragma unroll
            for (int j = 1; j < 8; j++) mx = fmaxf(mx, s[i][j]);
            mx = fmaxf(mx, __shfl_xor_sync(0xffffffffu, mx, 1));
            mx = fmaxf(mx, __shfl_xor_sync(0xffffffffu, mx, 2));
            mx = fmaxf(mx, __shfl_xor_sync(0xffffffffu, mx, 4));
            float mold = m_s[row];
            float mnew = fmaxf(mold, mx);
            float lsum = 0.f;
#pragma unroll
            for (int j = 0; j < 8; j++) {
                float p = __expf(s[i][j] - mnew);
                Ps[row * PS_STR + tx + 8 * j] = p;
                lsum += p;
            }
            lsum += __shfl_xor_sync(0xffffffffu, lsum, 1);
            lsum += __shfl_xor_sync(0xffffffffu, lsum, 2);
            lsum += __shfl_xor_sync(0xffffffffu, lsum, 4);
            if (tx == 0) {
                float alpha = __expf(mold - mnew);
                al_s[row] = alpha;
                l_s[row]  = l_s[row] * alpha + lsum;
                m_s[row]  = mnew;
            }
        }
        __syncthreads();

        float alpha[4];
#pragma unroll
        for (int i = 0; i < 4; i++) alpha[i] = al_s[ty + 16 * i];
#pragma unroll
        for (int i = 0; i < 4; i++)
#pragma unroll
            for (int d = 0; d < 16; d++) Oacc[i][d] *= alpha[i];

        const int d0 = tx * 16;
#pragma unroll 2
        for (int j = 0; j < 64; j++) {
            float4 v0 = *(const float4*)(Vs + j * QS_STR + d0);
            float4 v1 = *(const float4*)(Vs + j * QS_STR + d0 + 4);
            float4 v2 = *(const float4*)(Vs + j * QS_STR + d0 + 8);
            float4 v3 = *(const float4*)(Vs + j * QS_STR + d0 + 12);
            float p[4];
#pragma unroll
            for (int i = 0; i < 4; i++) p[i] = Ps[(ty + 16 * i) * PS_STR + j];
#pragma unroll
            for (int i = 0; i < 4; i++) {
                Oacc[i][0]  += p[i] * v0.x;  Oacc[i][1]  += p[i] * v0.y;
                Oacc[i][2]  += p[i] * v0.z;  Oacc[i][3]  += p[i] * v0.w;
                Oacc[i][4]  += p[i] * v1.x;  Oacc[i][5]  += p[i] * v1.y;
                Oacc[i][6]  += p[i] * v1.z;  Oacc[i][7]  += p[i] * v1.w;
                Oacc[i][8]  += p[i] * v2.x;  Oacc[i][9]  += p[i] * v2.y;
                Oacc[i][10] += p[i] * v2.z;  Oacc[i][11] += p[i] * v2.w;
                Oacc[i][12] += p[i] * v3.x;  Oacc[i][13] += p[i] * v3.y;
                Oacc[i][14] += p[i] * v3.z;  Oacc[i][15] += p[i] * v3.w;
            }
        }
        __syncthreads();
    }

#pragma unroll
    for (int i = 0; i < 4; i++) {
        int r = ty + 16 * i;
        float inv = 1.f / l_s[r];
        int t = it * 64 + r;
        float* op = g_att + ((size_t)b * Tt + t) * Cc + h * Dd + tx * 16;
        float4 w;
#pragma unroll
        for (int g = 0; g < 4; g++) {
            w.x = Oacc[i][4 * g + 0] * inv;
            w.y = Oacc[i][4 * g + 1] * inv;
            w.z = Oacc[i][4 * g + 2] * inv;
            w.w = Oacc[i][4 * g + 3] * inv;
            *(float4*)(op + 4 * g) = w;
        }
    }
}

// ---------------- launch ----------------------------------------------------
extern "C" void kernel_launch(void* const* d_in, const int* in_sizes, int n_in,
                              void* d_out, int out_size) {
    const float* x  = (const float*)d_in[0];
    const float* Wq = (const float*)d_in[1];
    const float* Wk = (const float*)d_in[2];
    const float* Wv = (const float*)d_in[3];
    const float* Wo = (const float*)d_in[4];
    float* out = (float*)d_out;

    float *pq, *pk, *pv, *patt;
    cudaGetSymbolAddress((void**)&pq,   g_q);
    cudaGetSymbolAddress((void**)&pk,   g_k);
    cudaGetSymbolAddress((void**)&pv,   g_v);
    cudaGetSymbolAddress((void**)&patt, g_att);

    const int M = Bb * Tt;                 // 4096
    const int gemm_smem = 2 * STAGE_B;     // 81920
    cudaFuncSetAttribute(gemm_hmma_kernel<0>,
                         cudaFuncAttributeMaxDynamicSharedMemorySize, gemm_smem);
    cudaFuncSetAttribute(gemm_hmma_kernel<1>,
                         cudaFuncAttributeMaxDynamicSharedMemorySize, gemm_smem);

    // 1. RoPE tables
    rope_tables_kernel<<<(Tt * 64 + 255) / 256, 256>>>();

    // 2. projections (HMMA split-bf16)
    gemm_hmma_kernel<1><<<dim3(Cc / 128, M / 128), 256, gemm_smem>>>(x, Wq, pq, M, Cc, Cc, Hh);
    gemm_hmma_kernel<1><<<dim3((KVh * Dd) / 128, M / 128), 256, gemm_smem>>>(x, Wk, pk, M, KVh * Dd, Cc, KVh);
    gemm_hmma_kernel<1><<<dim3((KVh * Dd) / 128, M / 128), 256, gemm_smem>>>(x, Wv, pv, M, KVh * Dd, Cc, KVh);

    // 3. RoPE on q and k
    rope_apply_kernel<<<(Bb * Hh * Tt * 64 + 255) / 256, 256>>>(pq, Hh);
    rope_apply_kernel<<<(Bb * KVh * Tt * 64 + 255) / 256, 256>>>(pk, KVh);

    // 4. flash attention (fp32)
    const int fa_smem = (3 * 64 * QS_STR + 64 * PS_STR + 3 * 64) * (int)sizeof(float);
    cudaFuncSetAttribute(flash_attn_kernel,
                         cudaFuncAttributeMaxDynamicSharedMemorySize, fa_smem);
    flash_attn_kernel<<<dim3(Tt / 64, Hh, Bb), 128, fa_smem>>>();

    // 5. output projection
    gemm_hmma_kernel<0><<<dim3(Cc / 128, M / 128), 256, gemm_smem>>>(patt, Wo, out, M, Cc, Cc, 0);
}

// round 4
// speedup vs baseline: 1.7912x; 1.1327x over previous
#include <cuda_runtime.h>
#include <cuda_bf16.h>
#include <math.h>
#include <stdint.h>

#define Bb  2
#define Tt  2048
#define Cc  2048
#define Hh  16
#define KVh 4
#define Dd  128
#define REP 4   // Hh / KVh

// ---------------- scratch (device globals; no allocation allowed) ----------
__device__ float g_cos[Tt * 64];
__device__ float g_sin[Tt * 64];
__device__ float g_q[(size_t)Bb * Hh  * Tt * Dd];   // (b,h,t,d)
__device__ float g_k[(size_t)Bb * KVh * Tt * Dd];   // (b,kv,t,d)
__device__ float g_v[(size_t)Bb * KVh * Tt * Dd];
__device__ float g_att[(size_t)Bb * Tt * Cc];       // (b*t, h*d) row-major

// ---------------- RoPE tables ----------------------------------------------
__global__ void rope_tables_kernel() {
    int idx = blockIdx.x * blockDim.x + threadIdx.x;
    if (idx >= Tt * 64) return;
    int t = idx / 64, i = idx % 64;
    double inv = pow(10000.0, -(double)(2 * i) / 128.0);
    double ang = (double)t * inv;
    g_cos[idx] = (float)cos(ang);
    g_sin[idx] = (float)sin(ang);
}

// ---------------- RoPE apply (in place, layout (bh, t, d)) ------------------
__global__ void rope_apply_kernel(float* buf, int nheads) {
    int idx = blockIdx.x * blockDim.x + threadIdx.x;
    int total = Bb * nheads * Tt * 64;
    if (idx >= total) return;
    int d  = idx & 63;
    int t  = (idx >> 6) & (Tt - 1);
    int bh = idx / (64 * Tt);
    float c = g_cos[t * 64 + d];
    float s = g_sin[t * 64 + d];
    float* p = buf + ((size_t)bh * Tt + t) * Dd;
    float x1 = p[d], x2 = p[d + 64];
    p[d]      = x1 * c - x2 * s;
    p[d + 64] = x2 * c + x1 * s;
}

// ======================= HMMA helpers ======================================
__device__ __forceinline__ void mma16816(float* c, const uint32_t* a, const uint32_t* b) {
    asm volatile(
        "mma.sync.aligned.m16n8k16.row.col.f32.bf16.bf16.f32 "
        "{%0,%1,%2,%3}, {%4,%5,%6,%7}, {%8,%9}, {%0,%1,%2,%3};"
        : "+f"(c[0]), "+f"(c[1]), "+f"(c[2]), "+f"(c[3])
        : "r"(a[0]), "r"(a[1]), "r"(a[2]), "r"(a[3]), "r"(b[0]), "r"(b[1]));
}
__device__ __forceinline__ void mma16816b(float* c, const uint32_t* a,
                                          uint32_t b0, uint32_t b1) {
    asm volatile(
        "mma.sync.aligned.m16n8k16.row.col.f32.bf16.bf16.f32 "
        "{%0,%1,%2,%3}, {%4,%5,%6,%7}, {%8,%9}, {%0,%1,%2,%3};"
        : "+f"(c[0]), "+f"(c[1]), "+f"(c[2]), "+f"(c[3])
        : "r"(a[0]), "r"(a[1]), "r"(a[2]), "r"(a[3]), "r"(b0), "r"(b1));
}

__device__ __forceinline__ void ldsm_x4(uint32_t& r0, uint32_t& r1, uint32_t& r2,
                                        uint32_t& r3, uint32_t addr) {
    asm volatile("ldmatrix.sync.aligned.m8n8.x4.shared.b16 {%0,%1,%2,%3}, [%4];"
                 : "=r"(r0), "=r"(r1), "=r"(r2), "=r"(r3) : "r"(addr));
}
__device__ __forceinline__ void ldsm_x4_t(uint32_t& r0, uint32_t& r1, uint32_t& r2,
                                          uint32_t& r3, uint32_t addr) {
    asm volatile("ldmatrix.sync.aligned.m8n8.x4.trans.shared.b16 {%0,%1,%2,%3}, [%4];"
                 : "=r"(r0), "=r"(r1), "=r"(r2), "=r"(r3) : "r"(addr));
}
__device__ __forceinline__ void ldsm_x2(uint32_t& r0, uint32_t& r1, uint32_t addr) {
    asm volatile("ldmatrix.sync.aligned.m8n8.x2.shared.b16 {%0,%1}, [%2];"
                 : "=r"(r0), "=r"(r1) : "r"(addr));
}

__device__ __forceinline__ uint32_t smem_u32_(const void* p) {
    uint32_t a;
    asm("{ .reg .u64 t; cvta.to.shared.u64 t, %1; cvt.u32.u64 %0, t; }"
        : "=r"(a) : "l"(p));
    return a;
}

// pack two floats to bf16x2 (x -> low half)
__device__ __forceinline__ uint32_t pack_bf16x2(float lo, float hi) {
    uint32_t r;
    asm("cvt.rn.bf16x2.f32 %0, %1, %2;" : "=r"(r) : "f"(hi), "f"(lo));
    return r;
}

// split 4 floats into hi/lo bf16x2 pairs
__device__ __forceinline__ void split4(float4 v, uint32_t* h2, uint32_t* l2) {
    __nv_bfloat16 e0 = __float2bfloat16(v.x), e1 = __float2bfloat16(v.y);
    __nv_bfloat16 e2 = __float2bfloat16(v.z), e3 = __float2bfloat16(v.w);
    h2[0] = ((uint32_t)__bfloat16_as_ushort(e1) << 16) | __bfloat16_as_ushort(e0);
    h2[1] = ((uint32_t)__bfloat16_as_ushort(e3) << 16) | __bfloat16_as_ushort(e2);
    l2[0] = pack_bf16x2(v.x - __bfloat162float(e0), v.y - __bfloat162float(e1));
    l2[1] = pack_bf16x2(v.z - __bfloat162float(e2), v.w - __bfloat162float(e3));
}

// convert+store 16 consecutive floats (scaled) into hi/lo bf16 smem
__device__ __forceinline__ void split_store16(const float* gsrc, char* hi, char* lo,
                                              uint32_t byteOff, float scale) {
    uint32_t H[8], L[8];
#pragma unroll
    for (int g = 0; g < 4; g++) {
        float4 v = ((const float4*)gsrc)[g];
        v.x *= scale; v.y *= scale; v.z *= scale; v.w *= scale;
        split4(v, H + 2 * g, L + 2 * g);
    }
    *(uint4*)(hi + byteOff)      = *(uint4*)&H[0];
    *(uint4*)(hi + byteOff + 16) = *(uint4*)&H[4];
    *(uint4*)(lo + byteOff)      = *(uint4*)&L[0];
    *(uint4*)(lo + byteOff + 16) = *(uint4*)&L[4];
}

// ======================= HMMA split-bf16 GEMM ===============================
#define BK      32
#define LDH     40                 // smem stride in halves (32 + 8 pad)
#define TILE_B  (128 * LDH * 2)    // 10240
#define STAGE_B (4 * TILE_B)       // 40960

template <int MODE>
__global__ void __launch_bounds__(256, 1)
gemm_hmma_kernel(const float* __restrict__ A, const float* __restrict__ Bm,
                 float* __restrict__ Cout, int M, int N, int K, int nh)
{
    extern __shared__ char smem[];
    const uint32_t sb = smem_u32_(smem);

    const int tid  = threadIdx.x;
    const int wid  = tid >> 5;
    const int lane = tid & 31;
    const int wr   = wid >> 2;
    const int wc   = wid & 3;
    const int m0   = blockIdx.y * 128;
    const int n0   = blockIdx.x * 128;

    const int srow = tid >> 1;
    const int sseg = tid & 1;
    const float* aptr = A  + (size_t)(m0 + srow) * K + sseg * 16;
    const float* bptr = Bm + (size_t)(n0 + srow) * K + sseg * 16;

    float acc[4][4][4];
#pragma unroll
    for (int i = 0; i < 4; i++)
#pragma unroll
        for (int j = 0; j < 4; j++)
#pragma unroll
            for (int q = 0; q < 4; q++) acc[i][j][q] = 0.f;

    const int NC = K / BK;

    auto store_chunk = [&](const float4* ga, const float4* gb, int stage) {
        uint32_t hA[8], lA[8], hB[8], lB[8];
#pragma unroll
        for (int g = 0; g < 4; g++) split4(ga[g], hA + 2*g, lA + 2*g);
#pragma unroll
        for (int g = 0; g < 4; g++) split4(gb[g], hB + 2*g, lB + 2*g);
        char* st = smem + stage * STAGE_B;
        uint32_t off = (uint32_t)(srow * LDH + sseg * 16) * 2;
        *(uint4*)(st + 0*TILE_B + off)      = *(uint4*)&hA[0];
        *(uint4*)(st + 0*TILE_B + off + 16) = *(uint4*)&hA[4];
        *(uint4*)(st + 1*TILE_B + off)      = *(uint4*)&lA[0];
        *(uint4*)(st + 1*TILE_B + off + 16) = *(uint4*)&lA[4];
        *(uint4*)(st + 2*TILE_B + off)      = *(uint4*)&hB[0];
        *(uint4*)(st + 2*TILE_B + off + 16) = *(uint4*)&hB[4];
        *(uint4*)(st + 3*TILE_B + off)      = *(uint4*)&lB[0];
        *(uint4*)(st + 3*TILE_B + off + 16) = *(uint4*)&lB[4];
    };

    float4 ga[4], gb[4];
#pragma unroll
    for (int g = 0; g < 4; g++) {
        ga[g] = *(const float4*)(aptr + g * 4);
        gb[g] = *(const float4*)(bptr + g * 4);
    }
    store_chunk(ga, gb, 0);
    __syncthreads();

    const uint32_t a_row = wr * 64 + (lane & 15);
    const uint32_t a_kh  = (lane >> 4) * 8;
    const uint32_t b_row = wc * 32 + (lane & 7);
    const uint32_t b_kh  = ((lane >> 3) & 1) * 8;

    for (int i = 0; i < NC; i++) {
        const int s = i & 1;
        if (i + 1 < NC) {
            const int kk = (i + 1) * BK;
#pragma unroll
            for (int g = 0; g < 4; g++) {
                ga[g] = *(const float4*)(aptr + kk + g * 4);
                gb[g] = *(const float4*)(bptr + kk + g * 4);
            }
        }

        const uint32_t stb = sb + s * STAGE_B;
#pragma unroll
        for (int kstep = 0; kstep < 2; kstep++) {
            const uint32_t kof = kstep * 16;
            uint32_t ahi[4][4], alo[4][4], bhi[4][2], blo[4][2];
#pragma unroll
            for (int mt = 0; mt < 4; mt++) {
                uint32_t ad = stb + ((a_row + mt * 16) * LDH + kof + a_kh) * 2;
                ldsm_x4(ahi[mt][0], ahi[mt][1], ahi[mt][2], ahi[mt][3], ad + 0 * TILE_B);
                ldsm_x4(alo[mt][0], alo[mt][1], alo[mt][2], alo[mt][3], ad + 1 * TILE_B);
            }
#pragma unroll
            for (int nt = 0; nt < 4; nt++) {
                uint32_t bd = stb + ((b_row + nt * 8) * LDH + kof + b_kh) * 2;
                ldsm_x2(bhi[nt][0], bhi[nt][1], bd + 2 * TILE_B);
                ldsm_x2(blo[nt][0], blo[nt][1], bd + 3 * TILE_B);
            }
#pragma unroll
            for (int mt = 0; mt < 4; mt++)
#pragma unroll
                for (int nt = 0; nt < 4; nt++) {
                    mma16816(acc[mt][nt], ahi[mt], bhi[nt]);
                    mma16816(acc[mt][nt], ahi[mt], blo[nt]);
                    mma16816(acc[mt][nt], alo[mt], bhi[nt]);
                }
        }
        __syncthreads();
        if (i + 1 < NC) {
            store_chunk(ga, gb, s ^ 1);
            __syncthreads();
        }
    }

#pragma unroll
    for (int mt = 0; mt < 4; mt++) {
        const int r0 = m0 + wr * 64 + mt * 16 + (lane >> 2);
        const int r1 = r0 + 8;
#pragma unroll
        for (int nt = 0; nt < 4; nt++) {
            const int c = n0 + wc * 32 + nt * 8 + (lane & 3) * 2;
            if (MODE == 0) {
                *(float2*)(Cout + (size_t)r0 * N + c) = make_float2(acc[mt][nt][0], acc[mt][nt][1]);
                *(float2*)(Cout + (size_t)r1 * N + c) = make_float2(acc[mt][nt][2], acc[mt][nt][3]);
            } else {
                const int h = c >> 7, d = c & 127;
                const int b0_ = r0 / Tt, t0_ = r0 & (Tt - 1);
                const int b1_ = r1 / Tt, t1_ = r1 & (Tt - 1);
                *(float2*)(Cout + (((size_t)b0_ * nh + h) * Tt + t0_) * Dd + d) =
                    make_float2(acc[mt][nt][0], acc[mt][nt][1]);
                *(float2*)(Cout + (((size_t)b1_ * nh + h) * Tt + t1_) * Dd + d) =
                    make_float2(acc[mt][nt][2], acc[mt][nt][3]);
            }
        }
    }
}

// ================= HMMA split-bf16 flash attention ==========================
// Block: 64 q-rows, 4 warps (16 rows each). KV tiles of 64. D=128.
// Q (scaled) hi/lo frags in registers; K/V hi/lo in smem per tile; P hi/lo in
// registers (accumulator layout == A-frag layout).

#define FA_LDH  136                    // 128 + 8 pad (halves)
#define FA_TILE (64 * FA_LDH * 2)      // 17408 bytes

__global__ void __launch_bounds__(128, 1)
flash_hmma_kernel() {
    extern __shared__ char smem[];
    char* KHI = smem;
    char* KLO = smem + FA_TILE;
    char* VHI = smem + 2 * FA_TILE;
    char* VLO = smem + 3 * FA_TILE;
    const uint32_t sKHI = smem_u32_(KHI);
    const uint32_t sKLO = sKHI + FA_TILE;
    const uint32_t sVHI = sKHI + 2 * FA_TILE;
    const uint32_t sVLO = sKHI + 3 * FA_TILE;

    const int it = blockIdx.x;
    const int h  = blockIdx.y;
    const int b  = blockIdx.z;
    const int kvh = h / REP;

    const float* qp = g_q + (((size_t)b * Hh  + h)   * Tt + it * 64) * Dd;
    const float* kp = g_k + (((size_t)b * KVh + kvh) * Tt) * Dd;
    const float* vp = g_v + (((size_t)b * KVh + kvh) * Tt) * Dd;

    const int tid  = threadIdx.x;
    const int wq   = tid >> 5;      // warp: q-band
    const int lane = tid & 31;

    const int lrow = tid >> 1;               // load row 0..63
    const int lcol = (tid & 1) * 64;         // float col base
    const uint32_t lOff = (uint32_t)(lrow * FA_LDH + lcol) * 2;

    const float scale = 0.08838834764831845f;  // 1/sqrt(128)

    // ---- stage Q (scaled) into K smem area, pull frags into registers ------
    {
        const float* qrow = qp + (size_t)lrow * 128 + lcol;
#pragma unroll
        for (int c = 0; c < 4; c++)
            split_store16(qrow + c * 16, KHI, KLO, lOff + c * 32, scale);
    }
    __syncthreads();

    uint32_t qhi[8][4], qlo[8][4];
    {
        const uint32_t a_row = wq * 16 + (lane & 15);
        const uint32_t a_kh  = (lane >> 4) * 8;
#pragma unroll
        for (int ks = 0; ks < 8; ks++) {
            uint32_t ad = (a_row * FA_LDH + ks * 16 + a_kh) * 2;
            ldsm_x4(qhi[ks][0], qhi[ks][1], qhi[ks][2], qhi[ks][3], sKHI + ad);
            ldsm_x4(qlo[ks][0], qlo[ks][1], qlo[ks][2], qlo[ks][3], sKLO + ad);
        }
    }
    __syncthreads();

    // per-thread softmax state: rows r_a = wq*16 + (lane>>2), r_b = r_a + 8
    float m_a = -1e30f, m_b = -1e30f, l_a = 0.f, l_b = 0.f;
    float oacc[16][4];
#pragma unroll
    for (int nt = 0; nt < 16; nt++)
#pragma unroll
        for (int q = 0; q < 4; q++) oacc[nt][q] = 0.f;

    // ldmatrix lane addressing
    const uint32_t kb_row = (lane & 7) + ((lane >> 4) * 8);     // n row within pair
    const uint32_t kb_kh  = ((lane >> 3) & 1) * 8;              // k half
    const uint32_t vt_kv  = lane & 15;                          // kv within 16
    const uint32_t vt_dh  = (lane >> 4) * 8;                    // d half within 16

    for (int jt = 0; jt <= it; jt++) {
        // ---- load + convert K, V tile ------------------------------------
        {
            const float* krow = kp + (size_t)(jt * 64 + lrow) * 128 + lcol;
            const float* vrow = vp + (size_t)(jt * 64 + lrow) * 128 + lcol;
#pragma unroll
            for (int c = 0; c < 4; c++) {
                split_store16(krow + c * 16, KHI, KLO, lOff + c * 32, 1.f);
                split_store16(vrow + c * 16, VHI, VLO, lOff + c * 32, 1.f);
            }
        }
        __syncthreads();

        // ---- S = Q K^T (3-pass) ------------------------------------------
        float sacc[8][4];
#pragma unroll
        for (int nt = 0; nt < 8; nt++)
#pragma unroll
            for (int q = 0; q < 4; q++) sacc[nt][q] = 0.f;

#pragma unroll
        for (int ks = 0; ks < 8; ks++) {
#pragma unroll
            for (int ntp = 0; ntp < 4; ntp++) {
                uint32_t bd = ((ntp * 16 + kb_row) * FA_LDH + ks * 16 + kb_kh) * 2;
                uint32_t kh0, kh1, kh2, kh3, kl0, kl1, kl2, kl3;
                ldsm_x4(kh0, kh1, kh2, kh3, sKHI + bd);
                ldsm_x4(kl0, kl1, kl2, kl3, sKLO + bd);
                mma16816b(sacc[2*ntp],   qhi[ks], kh0, kh1);
                mma16816b(sacc[2*ntp],   qhi[ks], kl0, kl1);
                mma16816b(sacc[2*ntp],   qlo[ks], kh0, kh1);
                mma16816b(sacc[2*ntp+1], qhi[ks], kh2, kh3);
                mma16816b(sacc[2*ntp+1], qhi[ks], kl2, kl3);
                mma16816b(sacc[2*ntp+1], qlo[ks], kh2, kh3);
            }
        }

        // ---- causal mask on diagonal tile --------------------------------
        if (jt == it) {
            const int ra = wq * 16 + (lane >> 2);
#pragma unroll
            for (int nt = 0; nt < 8; nt++) {
                const int c0 = nt * 8 + (lane & 3) * 2;
                if (c0 > ra)     sacc[nt][0] = -1e30f;
                if (c0 + 1 > ra) sacc[nt][1] = -1e30f;
                if (c0 > ra + 8)     sacc[nt][2] = -1e30f;
                if (c0 + 1 > ra + 8) sacc[nt][3] = -1e30f;
            }
        }

        // ---- online softmax ----------------------------------------------
        float mx_a = -1e30f, mx_b = -1e30f;
#pragma unroll
        for (int nt = 0; nt < 8; nt++) {
            mx_a = fmaxf(mx_a, fmaxf(sacc[nt][0], sacc[nt][1]));
            mx_b = fmaxf(mx_b, fmaxf(sacc[nt][2], sacc[nt][3]));
        }
        mx_a = fmaxf(mx_a, __shfl_xor_sync(0xffffffffu, mx_a, 1));
        mx_a = fmaxf(mx_a, __shfl_xor_sync(0xffffffffu, mx_a, 2));
        mx_b = fmaxf(mx_b, __shfl_xor_sync(0xffffffffu, mx_b, 1));
        mx_b = fmaxf(mx_b, __shfl_xor_sync(0xffffffffu, mx_b, 2));

        const float mn_a = fmaxf(m_a, mx_a);
        const float mn_b = fmaxf(m_b, mx_b);
        const float al_a = __expf(m_a - mn_a);
        const float al_b = __expf(m_b - mn_b);
        m_a = mn_a; m_b = mn_b;

        float ls_a = 0.f, ls_b = 0.f;
#pragma unroll
        for (int nt = 0; nt < 8; nt++) {
            float p0 = __expf(sacc[nt][0] - mn_a);
            float p1 = __expf(sacc[nt][1] - mn_a);
            float p2 = __expf(sacc[nt][2] - mn_b);
            float p3 = __expf(sacc[nt][3] - mn_b);
            sacc[nt][0] = p0; sacc[nt][1] = p1; sacc[nt][2] = p2; sacc[nt][3] = p3;
            ls_a += p0 + p1; ls_b += p2 + p3;
        }
        ls_a += __shfl_xor_sync(0xffffffffu, ls_a, 1);
        ls_a += __shfl_xor_sync(0xffffffffu, ls_a, 2);
        ls_b += __shfl_xor_sync(0xffffffffu, ls_b, 1);
        ls_b += __shfl_xor_sync(0xffffffffu, ls_b, 2);
        l_a = l_a * al_a + ls_a;
        l_b = l_b * al_b + ls_b;

#pragma unroll
        for (int nt = 0; nt < 16; nt++) {
            oacc[nt][0] *= al_a; oacc[nt][1] *= al_a;
            oacc[nt][2] *= al_b; oacc[nt][3] *= al_b;
        }

        // ---- O += P V (3-pass) -------------------------------------------
#pragma unroll
        for (int kt = 0; kt < 4; kt++) {
            // P frags: A layout {a0: (ra, k0-7)... } from sacc[2kt], sacc[2kt+1]
            uint32_t phi[4], plo[4];
            {
                float* pa = sacc[2*kt];
                float* pb = sacc[2*kt + 1];
                __nv_bfloat16 e0, e1;
                e0 = __float2bfloat16(pa[0]); e1 = __float2bfloat16(pa[1]);
                phi[0] = ((uint32_t)__bfloat16_as_ushort(e1) << 16) | __bfloat16_as_ushort(e0);
                plo[0] = pack_bf16x2(pa[0] - __bfloat162float(e0), pa[1] - __bfloat162float(e1));
                e0 = __float2bfloat16(pa[2]); e1 = __float2bfloat16(pa[3]);
                phi[1] = ((uint32_t)__bfloat16_as_ushort(e1) << 16) | __bfloat16_as_ushort(e0);
                plo[1] = pack_bf16x2(pa[2] - __bfloat162float(e0), pa[3] - __bfloat162float(e1));
                e0 = __float2bfloat16(pb[0]); e1 = __float2bfloat16(pb[1]);
                phi[2] = ((uint32_t)__bfloat16_as_ushort(e1) << 16) | __bfloat16_as_ushort(e0);
                plo[2] = pack_bf16x2(pb[0] - __bfloat162float(e0), pb[1] - __bfloat162float(e1));
                e0 = __float2bfloat16(pb[2]); e1 = __float2bfloat16(pb[3]);
                phi[3] = ((uint32_t)__bfloat16_as_ushort(e1) << 16) | __bfloat16_as_ushort(e0);
                plo[3] = pack_bf16x2(pb[2] - __bfloat162float(e0), pb[3] - __bfloat162float(e1));
            }
#pragma unroll
            for (int ntp = 0; ntp < 8; ntp++) {
                uint32_t vd = ((kt * 16 + vt_kv) * FA_LDH + ntp * 16 + vt_dh) * 2;
                uint32_t vh0, vh1, vh2, vh3, vl0, vl1, vl2, vl3;
                ldsm_x4_t(vh0, vh1, vh2, vh3, sVHI + vd);
                ldsm_x4_t(vl0, vl1, vl2, vl3, sVLO + vd);
                mma16816b(oacc[2*ntp],   phi, vh0, vh1);
                mma16816b(oacc[2*ntp],   phi, vl0, vl1);
                mma16816b(oacc[2*ntp],   plo, vh0, vh1);
                mma16816b(oacc[2*ntp+1], phi, vh2, vh3);
                mma16816b(oacc[2*ntp+1], phi, vl2, vl3);
                mma16816b(oacc[2*ntp+1], plo, vh2, vh3);
            }
        }
        __syncthreads();
    }

    // ---- finalize: divide by l, write (b*t, h*d) ---------------------------
    const float inv_a = 1.f / l_a;
    const float inv_b = 1.f / l_b;
    const int ta = it * 64 + wq * 16 + (lane >> 2);
    const int tb = ta + 8;
    float* opa = g_att + ((size_t)b * Tt + ta) * Cc + h * Dd;
    float* opb = g_att + ((size_t)b * Tt + tb) * Cc + h * Dd;
#pragma unroll
    for (int nt = 0; nt < 16; nt++) {
        const int d = nt * 8 + (lane & 3) * 2;
        *(float2*)(opa + d) = make_float2(oacc[nt][0] * inv_a, oacc[nt][1] * inv_a);
        *(float2*)(opb + d) = make_float2(oacc[nt][2] * inv_b, oacc[nt][3] * inv_b);
    }
}

// ---------------- launch ----------------------------------------------------
extern "C" void kernel_launch(void* const* d_in, const int* in_sizes, int n_in,
                              void* d_out, int out_size) {
    const float* x  = (const float*)d_in[0];
    const float* Wq = (const float*)d_in[1];
    const float* Wk = (const float*)d_in[2];
    const float* Wv = (const float*)d_in[3];
    const float* Wo = (const float*)d_in[4];
    float* out = (float*)d_out;

    float *pq, *pk, *pv, *patt;
    cudaGetSymbolAddress((void**)&pq,   g_q);
    cudaGetSymbolAddress((void**)&pk,   g_k);
    cudaGetSymbolAddress((void**)&pv,   g_v);
    cudaGetSymbolAddress((void**)&patt, g_att);

    const int M = Bb * Tt;                 // 4096
    const int gemm_smem = 2 * STAGE_B;     // 81920
    cudaFuncSetAttribute(gemm_hmma_kernel<0>,
                         cudaFuncAttributeMaxDynamicSharedMemorySize, gemm_smem);
    cudaFuncSetAttribute(gemm_hmma_kernel<1>,
                         cudaFuncAttributeMaxDynamicSharedMemorySize, gemm_smem);

    // 1. RoPE tables
    rope_tables_kernel<<<(Tt * 64 + 255) / 256, 256>>>();

    // 2. projections (HMMA split-bf16)
    gemm_hmma_kernel<1><<<dim3(Cc / 128, M / 128), 256, gemm_smem>>>(x, Wq, pq, M, Cc, Cc, Hh);
    gemm_hmma_kernel<1><<<dim3((KVh * Dd) / 128, M / 128), 256, gemm_smem>>>(x, Wk, pk, M, KVh * Dd, Cc, KVh);
    gemm_hmma_kernel<1><<<dim3((KVh * Dd) / 128, M / 128), 256, gemm_smem>>>(x, Wv, pv, M, KVh * Dd, Cc, KVh);

    // 3. RoPE on q and k
    rope_apply_kernel<<<(Bb * Hh * Tt * 64 + 255) / 256, 256>>>(pq, Hh);
    rope_apply_kernel<<<(Bb * KVh * Tt * 64 + 255) / 256, 256>>>(pk, KVh);

    // 4. flash attention (HMMA split-bf16)
    const int fa_smem = 4 * FA_TILE;       // 69632
    cudaFuncSetAttribute(flash_hmma_kernel,
                         cudaFuncAttributeMaxDynamicSharedMemorySize, fa_smem);
    flash_hmma_kernel<<<dim3(Tt / 64, Hh, Bb), 128, fa_smem>>>();

    // 5. output projection
    gemm_hmma_kernel<0><<<dim3(Cc / 128, M / 128), 256, gemm_smem>>>(patt, Wo, out, M, Cc, Cc, 0);
}

// round 5
// speedup vs baseline: 3.3467x; 1.8684x over previous
#include <cuda_runtime.h>
#include <cuda_bf16.h>
#include <math.h>
#include <stdint.h>

#define Bb  2
#define Tt  2048
#define Cc  2048
#define Hh  16
#define KVh 4
#define Dd  128
#define REP 4   // Hh / KVh

// ---------------- scratch (device globals; no allocation allowed) ----------
__device__ float g_cos[Tt * 64];
__device__ float g_sin[Tt * 64];
__device__ float g_q[(size_t)Bb * Hh  * Tt * Dd];   // (b,h,t,d) fp32 (pre-rope)
__device__ float g_k[(size_t)Bb * KVh * Tt * Dd];
__device__ float g_v[(size_t)Bb * KVh * Tt * Dd];
__device__ float g_att[(size_t)Bb * Tt * Cc];       // (b*t, h*d) row-major

// bf16 hi/lo pre-converted operands for flash attention
__device__ __nv_bfloat16 g_qh[(size_t)Bb * Hh  * Tt * Dd];
__device__ __nv_bfloat16 g_ql[(size_t)Bb * Hh  * Tt * Dd];
__device__ __nv_bfloat16 g_kh[(size_t)Bb * KVh * Tt * Dd];
__device__ __nv_bfloat16 g_kl[(size_t)Bb * KVh * Tt * Dd];
__device__ __nv_bfloat16 g_vh[(size_t)Bb * KVh * Tt * Dd];
__device__ __nv_bfloat16 g_vl[(size_t)Bb * KVh * Tt * Dd];

// ---------------- RoPE tables ----------------------------------------------
__global__ void rope_tables_kernel() {
    int idx = blockIdx.x * blockDim.x + threadIdx.x;
    if (idx >= Tt * 64) return;
    int t = idx / 64, i = idx % 64;
    double inv = pow(10000.0, -(double)(2 * i) / 128.0);
    double ang = (double)t * inv;
    g_cos[idx] = (float)cos(ang);
    g_sin[idx] = (float)sin(ang);
}

// ======================= helpers ===========================================
__device__ __forceinline__ uint32_t smem_u32_(const void* p) {
    uint32_t a;
    asm("{ .reg .u64 t; cvta.to.shared.u64 t, %1; cvt.u32.u64 %0, t; }"
        : "=r"(a) : "l"(p));
    return a;
}
__device__ __forceinline__ uint32_t pack_bf16x2(float lo, float hi) {
    uint32_t r;
    asm("cvt.rn.bf16x2.f32 %0, %1, %2;" : "=r"(r) : "f"(hi), "f"(lo));
    return r;
}
__device__ __forceinline__ void split4(float4 v, uint32_t* h2, uint32_t* l2) {
    __nv_bfloat16 e0 = __float2bfloat16(v.x), e1 = __float2bfloat16(v.y);
    __nv_bfloat16 e2 = __float2bfloat16(v.z), e3 = __float2bfloat16(v.w);
    h2[0] = ((uint32_t)__bfloat16_as_ushort(e1) << 16) | __bfloat16_as_ushort(e0);
    h2[1] = ((uint32_t)__bfloat16_as_ushort(e3) << 16) | __bfloat16_as_ushort(e2);
    l2[0] = pack_bf16x2(v.x - __bfloat162float(e0), v.y - __bfloat162float(e1));
    l2[1] = pack_bf16x2(v.z - __bfloat162float(e2), v.w - __bfloat162float(e3));
}

__device__ __forceinline__ void mma16816(float* c, const uint32_t* a, const uint32_t* b) {
    asm volatile(
        "mma.sync.aligned.m16n8k16.row.col.f32.bf16.bf16.f32 "
        "{%0,%1,%2,%3}, {%4,%5,%6,%7}, {%8,%9}, {%0,%1,%2,%3};"
        : "+f"(c[0]), "+f"(c[1]), "+f"(c[2]), "+f"(c[3])
        : "r"(a[0]), "r"(a[1]), "r"(a[2]), "r"(a[3]), "r"(b[0]), "r"(b[1]));
}
__device__ __forceinline__ void mma16816b(float* c, const uint32_t* a,
                                          uint32_t b0, uint32_t b1) {
    asm volatile(
        "mma.sync.aligned.m16n8k16.row.col.f32.bf16.bf16.f32 "
        "{%0,%1,%2,%3}, {%4,%5,%6,%7}, {%8,%9}, {%0,%1,%2,%3};"
        : "+f"(c[0]), "+f"(c[1]), "+f"(c[2]), "+f"(c[3])
        : "r"(a[0]), "r"(a[1]), "r"(a[2]), "r"(a[3]), "r"(b0), "r"(b1));
}
__device__ __forceinline__ void ldsm_x4(uint32_t& r0, uint32_t& r1, uint32_t& r2,
                                        uint32_t& r3, uint32_t addr) {
    asm volatile("ldmatrix.sync.aligned.m8n8.x4.shared.b16 {%0,%1,%2,%3}, [%4];"
                 : "=r"(r0), "=r"(r1), "=r"(r2), "=r"(r3) : "r"(addr));
}
__device__ __forceinline__ void ldsm_x4_t(uint32_t& r0, uint32_t& r1, uint32_t& r2,
                                          uint32_t& r3, uint32_t addr) {
    asm volatile("ldmatrix.sync.aligned.m8n8.x4.trans.shared.b16 {%0,%1,%2,%3}, [%4];"
                 : "=r"(r0), "=r"(r1), "=r"(r2), "=r"(r3) : "r"(addr));
}
__device__ __forceinline__ void ldsm_x2(uint32_t& r0, uint32_t& r1, uint32_t addr) {
    asm volatile("ldmatrix.sync.aligned.m8n8.x2.shared.b16 {%0,%1}, [%2];"
                 : "=r"(r0), "=r"(r1) : "r"(addr));
}
__device__ __forceinline__ void cp16(uint32_t dst, const void* src) {
    asm volatile("cp.async.cg.shared.global [%0], [%1], 16;" :: "r"(dst), "l"(src));
}
#define CP_COMMIT() asm volatile("cp.async.commit_group;" ::: "memory")
#define CP_WAIT(n)  asm volatile("cp.async.wait_group %0;" :: "n"(n) : "memory")

// convert+store 16 consecutive floats into hi/lo bf16 smem (GEMM staging)
__device__ __forceinline__ void split_store16(const float* gsrc, char* hi, char* lo,
                                              uint32_t byteOff) {
    uint32_t H[8], L[8];
#pragma unroll
    for (int g = 0; g < 4; g++) {
        float4 v = ((const float4*)gsrc)[g];
        split4(v, H + 2 * g, L + 2 * g);
    }
    *(uint4*)(hi + byteOff)      = *(uint4*)&H[0];
    *(uint4*)(hi + byteOff + 16) = *(uint4*)&H[4];
    *(uint4*)(lo + byteOff)      = *(uint4*)&L[0];
    *(uint4*)(lo + byteOff + 16) = *(uint4*)&L[4];
}

// ---------------- RoPE + split conversion -----------------------------------
// q/k: rotate, (scale), split into hi/lo bf16.
__global__ void rope_split_kernel(const float* __restrict__ src,
                                  __nv_bfloat16* __restrict__ dh,
                                  __nv_bfloat16* __restrict__ dl,
                                  int nheads, float scale) {
    int idx = blockIdx.x * blockDim.x + threadIdx.x;
    int total = Bb * nheads * Tt * 64;
    if (idx >= total) return;
    int d  = idx & 63;
    int t  = (idx >> 6) & (Tt - 1);
    int bh = idx / (64 * Tt);
    float c = g_cos[t * 64 + d];
    float s = g_sin[t * 64 + d];
    size_t base = ((size_t)bh * Tt + t) * Dd;
    float x1 = src[base + d], x2 = src[base + d + 64];
    float y1 = (x1 * c - x2 * s) * scale;
    float y2 = (x2 * c + x1 * s) * scale;
    __nv_bfloat16 h1 = __float2bfloat16(y1);
    __nv_bfloat16 h2 = __float2bfloat16(y2);
    dh[base + d]      = h1;
    dh[base + d + 64] = h2;
    dl[base + d]      = __float2bfloat16(y1 - __bfloat162float(h1));
    dl[base + d + 64] = __float2bfloat16(y2 - __bfloat162float(h2));
}

// v: plain split
__global__ void split_v_kernel() {
    int idx = blockIdx.x * blockDim.x + threadIdx.x;
    int total = Bb * KVh * Tt * Dd;
    if (idx >= total) return;
    float y = g_v[idx];
    __nv_bfloat16 h = __float2bfloat16(y);
    g_vh[idx] = h;
    g_vl[idx] = __float2bfloat16(y - __bfloat162float(h));
}

// ======================= HMMA split-bf16 GEMM ===============================
#define BK      32
#define LDH     40
#define TILE_B  (128 * LDH * 2)
#define STAGE_B (4 * TILE_B)

template <int MODE>
__global__ void __launch_bounds__(256, 1)
gemm_hmma_kernel(const float* __restrict__ A, const float* __restrict__ Bm,
                 float* __restrict__ Cout, int M, int N, int K, int nh)
{
    extern __shared__ char smem[];
    const uint32_t sb = smem_u32_(smem);

    const int tid  = threadIdx.x;
    const int wid  = tid >> 5;
    const int lane = tid & 31;
    const int wr   = wid >> 2;
    const int wc   = wid & 3;
    const int m0   = blockIdx.y * 128;
    const int n0   = blockIdx.x * 128;

    const int srow = tid >> 1;
    const int sseg = tid & 1;
    const float* aptr = A  + (size_t)(m0 + srow) * K + sseg * 16;
    const float* bptr = Bm + (size_t)(n0 + srow) * K + sseg * 16;

    float acc[4][4][4];
#pragma unroll
    for (int i = 0; i < 4; i++)
#pragma unroll
        for (int j = 0; j < 4; j++)
#pragma unroll
            for (int q = 0; q < 4; q++) acc[i][j][q] = 0.f;

    const int NC = K / BK;

    auto store_chunk = [&](const float4* ga, const float4* gb, int stage) {
        uint32_t hA[8], lA[8], hB[8], lB[8];
#pragma unroll
        for (int g = 0; g < 4; g++) split4(ga[g], hA + 2*g, lA + 2*g);
#pragma unroll
        for (int g = 0; g < 4; g++) split4(gb[g], hB + 2*g, lB + 2*g);
        char* st = smem + stage * STAGE_B;
        uint32_t off = (uint32_t)(srow * LDH + sseg * 16) * 2;
        *(uint4*)(st + 0*TILE_B + off)      = *(uint4*)&hA[0];
        *(uint4*)(st + 0*TILE_B + off + 16) = *(uint4*)&hA[4];
        *(uint4*)(st + 1*TILE_B + off)      = *(uint4*)&lA[0];
        *(uint4*)(st + 1*TILE_B + off + 16) = *(uint4*)&lA[4];
        *(uint4*)(st + 2*TILE_B + off)      = *(uint4*)&hB[0];
        *(uint4*)(st + 2*TILE_B + off + 16) = *(uint4*)&hB[4];
        *(uint4*)(st + 3*TILE_B + off)      = *(uint4*)&lB[0];
        *(uint4*)(st + 3*TILE_B + off + 16) = *(uint4*)&lB[4];
    };

    float4 ga[4], gb[4];
#pragma unroll
    for (int g = 0; g < 4; g++) {
        ga[g] = *(const float4*)(aptr + g * 4);
        gb[g] = *(const float4*)(bptr + g * 4);
    }
    store_chunk(ga, gb, 0);
    __syncthreads();

    const uint32_t a_row = wr * 64 + (lane & 15);
    const uint32_t a_kh  = (lane >> 4) * 8;
    const uint32_t b_row = wc * 32 + (lane & 7);
    const uint32_t b_kh  = ((lane >> 3) & 1) * 8;

    for (int i = 0; i < NC; i++) {
        const int s = i & 1;
        if (i + 1 < NC) {
            const int kk = (i + 1) * BK;
#pragma unroll
            for (int g = 0; g < 4; g++) {
                ga[g] = *(const float4*)(aptr + kk + g * 4);
                gb[g] = *(const float4*)(bptr + kk + g * 4);
            }
        }

        const uint32_t stb = sb + s * STAGE_B;
#pragma unroll
        for (int kstep = 0; kstep < 2; kstep++) {
            const uint32_t kof = kstep * 16;
            uint32_t ahi[4][4], alo[4][4], bhi[4][2], blo[4][2];
#pragma unroll
            for (int mt = 0; mt < 4; mt++) {
                uint32_t ad = stb + ((a_row + mt * 16) * LDH + kof + a_kh) * 2;
                ldsm_x4(ahi[mt][0], ahi[mt][1], ahi[mt][2], ahi[mt][3], ad + 0 * TILE_B);
                ldsm_x4(alo[mt][0], alo[mt][1], alo[mt][2], alo[mt][3], ad + 1 * TILE_B);
            }
#pragma unroll
            for (int nt = 0; nt < 4; nt++) {
                uint32_t bd = stb + ((b_row + nt * 8) * LDH + kof + b_kh) * 2;
                ldsm_x2(bhi[nt][0], bhi[nt][1], bd + 2 * TILE_B);
                ldsm_x2(blo[nt][0], blo[nt][1], bd + 3 * TILE_B);
            }
#pragma unroll
            for (int mt = 0; mt < 4; mt++)
#pragma unroll
                for (int nt = 0; nt < 4; nt++) {
                    mma16816(acc[mt][nt], ahi[mt], bhi[nt]);
                    mma16816(acc[mt][nt], ahi[mt], blo[nt]);
                    mma16816(acc[mt][nt], alo[mt], bhi[nt]);
                }
        }
        __syncthreads();
        if (i + 1 < NC) {
            store_chunk(ga, gb, s ^ 1);
            __syncthreads();
        }
    }

#pragma unroll
    for (int mt = 0; mt < 4; mt++) {
        const int r0 = m0 + wr * 64 + mt * 16 + (lane >> 2);
        const int r1 = r0 + 8;
#pragma unroll
        for (int nt = 0; nt < 4; nt++) {
            const int c = n0 + wc * 32 + nt * 8 + (lane & 3) * 2;
            if (MODE == 0) {
                *(float2*)(Cout + (size_t)r0 * N + c) = make_float2(acc[mt][nt][0], acc[mt][nt][1]);
                *(float2*)(Cout + (size_t)r1 * N + c) = make_float2(acc[mt][nt][2], acc[mt][nt][3]);
            } else {
                const int h = c >> 7, d = c & 127;
                const int b0_ = r0 / Tt, t0_ = r0 & (Tt - 1);
                const int b1_ = r1 / Tt, t1_ = r1 & (Tt - 1);
                *(float2*)(Cout + (((size_t)b0_ * nh + h) * Tt + t0_) * Dd + d) =
                    make_float2(acc[mt][nt][0], acc[mt][nt][1]);
                *(float2*)(Cout + (((size_t)b1_ * nh + h) * Tt + t1_) * Dd + d) =
                    make_float2(acc[mt][nt][2], acc[mt][nt][3]);
            }
        }
    }
}

// ================= HMMA flash attention, pre-converted bf16 =================
// Block: 128 q-rows, 8 warps (16 rows each). KV tile 64. D=128.
// Double-buffered cp.async stages; Q hi/lo frags in registers.

#define FB_LDH  136                    // halves per smem row (128 + 8 pad)
#define FB_ROW  (FB_LDH * 2)           // 272 bytes
#define FB_MAT  (64 * FB_ROW)          // 17408
#define FB_STG  (4 * FB_MAT)           // 69632 (Khi,Klo,Vhi,Vlo)
#define FB_QOFF (2 * FB_STG)           // Q region: qhi(128 rows), qlo(128 rows)
#define FB_SMEM (FB_QOFF + 2 * 128 * FB_ROW)   // 208896

__global__ void __launch_bounds__(256, 1)
flash_hmma2_kernel() {
    extern __shared__ char smem[];
    const uint32_t sb = smem_u32_(smem);

    const int it = (Tt / 128 - 1) - blockIdx.x;   // heavy blocks first
    const int h  = blockIdx.y;
    const int b  = blockIdx.z;
    const int kvh = h / REP;

    const __nv_bfloat16* qh = g_qh + (((size_t)b * Hh + h) * Tt + it * 128) * Dd;
    const __nv_bfloat16* ql = g_ql + (((size_t)b * Hh + h) * Tt + it * 128) * Dd;
    const __nv_bfloat16* kh = g_kh + ((size_t)b * KVh + kvh) * Tt * Dd;
    const __nv_bfloat16* kl = g_kl + ((size_t)b * KVh + kvh) * Tt * Dd;
    const __nv_bfloat16* vh = g_vh + ((size_t)b * KVh + kvh) * Tt * Dd;
    const __nv_bfloat16* vl = g_vl + ((size_t)b * KVh + kvh) * Tt * Dd;

    const int tid  = threadIdx.x;
    const int wq   = tid >> 5;
    const int lane = tid & 31;

    // ---- async copy of one 64-row KV tile into stage ----------------------
    auto load_tile = [&](int jt, int stg) {
        const uint32_t db = sb + stg * FB_STG;
        const size_t gb0 = (size_t)jt * 64 * Dd;
#pragma unroll
        for (int c = tid; c < 1024; c += 256) {
            const uint32_t d = db + (c >> 4) * FB_ROW + (c & 15) * 16;
            const size_t  o = gb0 + (c >> 4) * Dd + (c & 15) * 8;
            cp16(d + 0 * FB_MAT, kh + o);
            cp16(d + 1 * FB_MAT, kl + o);
            cp16(d + 2 * FB_MAT, vh + o);
            cp16(d + 3 * FB_MAT, vl + o);
        }
    };

    // ---- load Q (hi/lo) + first KV tile -----------------------------------
#pragma unroll
    for (int c = tid; c < 2048; c += 256) {
        const uint32_t d = sb + FB_QOFF + (c >> 4) * FB_ROW + (c & 15) * 16;
        const size_t  o = (size_t)(c >> 4) * Dd + (c & 15) * 8;
        cp16(d, qh + o);
        cp16(d + 128 * FB_ROW, ql + o);
    }
    load_tile(0, 0);
    CP_COMMIT();
    CP_WAIT(0);
    __syncthreads();

    // ---- Q fragments into registers ---------------------------------------
    uint32_t qhi[8][4], qlo[8][4];
    {
        const uint32_t a_row = wq * 16 + (lane & 15);
        const uint32_t a_kh  = (lane >> 4) * 8;
#pragma unroll
        for (int ks = 0; ks < 8; ks++) {
            uint32_t ad = sb + FB_QOFF + a_row * FB_ROW + (ks * 16 + a_kh) * 2;
            ldsm_x4(qhi[ks][0], qhi[ks][1], qhi[ks][2], qhi[ks][3], ad);
            ldsm_x4(qlo[ks][0], qlo[ks][1], qlo[ks][2], qlo[ks][3], ad + 128 * FB_ROW);
        }
    }

    float m_a = -1e30f, m_b = -1e30f, l_a = 0.f, l_b = 0.f;
    float oacc[16][4];
#pragma unroll
    for (int nt = 0; nt < 16; nt++)
#pragma unroll
        for (int q = 0; q < 4; q++) oacc[nt][q] = 0.f;

    const uint32_t kb_row = (lane & 7) + ((lane >> 4) * 8);
    const uint32_t kb_kh  = ((lane >> 3) & 1) * 8;
    const uint32_t vt_kv  = lane & 15;
    const uint32_t vt_dh  = (lane >> 4) * 8;

    const int jmax = 2 * it + 1;

    for (int jt = 0; jt <= jmax; jt++) {
        const int s = jt & 1;
        if (jt + 1 <= jmax) {
            load_tile(jt + 1, s ^ 1);
            CP_COMMIT();
            CP_WAIT(1);
        } else {
            CP_WAIT(0);
        }
        __syncthreads();

        const uint32_t sKHI = sb + s * FB_STG;
        const uint32_t sKLO = sKHI + FB_MAT;
        const uint32_t sVHI = sKHI + 2 * FB_MAT;
        const uint32_t sVLO = sKHI + 3 * FB_MAT;

        // ---- S = Q K^T (3-pass) ------------------------------------------
        float sacc[8][4];
#pragma unroll
        for (int nt = 0; nt < 8; nt++)
#pragma unroll
            for (int q = 0; q < 4; q++) sacc[nt][q] = 0.f;

#pragma unroll
        for (int ks = 0; ks < 8; ks++) {
#pragma unroll
            for (int ntp = 0; ntp < 4; ntp++) {
                uint32_t bd = ((ntp * 16 + kb_row) * FB_LDH + ks * 16 + kb_kh) * 2;
                uint32_t kh0, kh1, kh2, kh3, kl0, kl1, kl2, kl3;
                ldsm_x4(kh0, kh1, kh2, kh3, sKHI + bd);
                ldsm_x4(kl0, kl1, kl2, kl3, sKLO + bd);
                mma16816b(sacc[2*ntp],   qhi[ks], kh0, kh1);
                mma16816b(sacc[2*ntp],   qhi[ks], kl0, kl1);
                mma16816b(sacc[2*ntp],   qlo[ks], kh0, kh1);
                mma16816b(sacc[2*ntp+1], qhi[ks], kh2, kh3);
                mma16816b(sacc[2*ntp+1], qhi[ks], kl2, kl3);
                mma16816b(sacc[2*ntp+1], qlo[ks], kh2, kh3);
            }
        }

        // ---- causal mask --------------------------------------------------
        if (jt >= 2 * it) {
            const int ra = it * 128 + wq * 16 + (lane >> 2);
            const int cb = jt * 64 + (lane & 3) * 2;
#pragma unroll
            for (int nt = 0; nt < 8; nt++) {
                const int c0 = cb + nt * 8;
                if (c0 > ra)         sacc[nt][0] = -1e30f;
                if (c0 + 1 > ra)     sacc[nt][1] = -1e30f;
                if (c0 > ra + 8)     sacc[nt][2] = -1e30f;
                if (c0 + 1 > ra + 8) sacc[nt][3] = -1e30f;
            }
        }

        // ---- online softmax ----------------------------------------------
        float mx_a = -1e30f, mx_b = -1e30f;
#pragma unroll
        for (int nt = 0; nt < 8; nt++) {
            mx_a = fmaxf(mx_a, fmaxf(sacc[nt][0], sacc[nt][1]));
            mx_b = fmaxf(mx_b, fmaxf(sacc[nt][2], sacc[nt][3]));
        }
        mx_a = fmaxf(mx_a, __shfl_xor_sync(0xffffffffu, mx_a, 1));
        mx_a = fmaxf(mx_a, __shfl_xor_sync(0xffffffffu, mx_a, 2));
        mx_b = fmaxf(mx_b, __shfl_xor_sync(0xffffffffu, mx_b, 1));
        mx_b = fmaxf(mx_b, __shfl_xor_sync(0xffffffffu, mx_b, 2));

        const float mn_a = fmaxf(m_a, mx_a);
        const float mn_b = fmaxf(m_b, mx_b);
        const float al_a = __expf(m_a - mn_a);
        const float al_b = __expf(m_b - mn_b);
        m_a = mn_a; m_b = mn_b;

        float ls_a = 0.f, ls_b = 0.f;
#pragma unroll
        for (int nt = 0; nt < 8; nt++) {
            float p0 = __expf(sacc[nt][0] - mn_a);
            float p1 = __expf(sacc[nt][1] - mn_a);
            float p2 = __expf(sacc[nt][2] - mn_b);
            float p3 = __expf(sacc[nt][3] - mn_b);
            sacc[nt][0] = p0; sacc[nt][1] = p1; sacc[nt][2] = p2; sacc[nt][3] = p3;
            ls_a += p0 + p1; ls_b += p2 + p3;
        }
        ls_a += __shfl_xor_sync(0xffffffffu, ls_a, 1);
        ls_a += __shfl_xor_sync(0xffffffffu, ls_a, 2);
        ls_b += __shfl_xor_sync(0xffffffffu, ls_b, 1);
        ls_b += __shfl_xor_sync(0xffffffffu, ls_b, 2);
        l_a = l_a * al_a + ls_a;
        l_b = l_b * al_b + ls_b;

#pragma unroll
        for (int nt = 0; nt < 16; nt++) {
            oacc[nt][0] *= al_a; oacc[nt][1] *= al_a;
            oacc[nt][2] *= al_b; oacc[nt][3] *= al_b;
        }

        // ---- O += P V (3-pass) -------------------------------------------
#pragma unroll
        for (int kt = 0; kt < 4; kt++) {
            uint32_t phi[4], plo[4];
            {
                float* pa = sacc[2*kt];
                float* pb = sacc[2*kt + 1];
                __nv_bfloat16 e0, e1;
                e0 = __float2bfloat16(pa[0]); e1 = __float2bfloat16(pa[1]);
                phi[0] = ((uint32_t)__bfloat16_as_ushort(e1) << 16) | __bfloat16_as_ushort(e0);
                plo[0] = pack_bf16x2(pa[0] - __bfloat162float(e0), pa[1] - __bfloat162float(e1));
                e0 = __float2bfloat16(pa[2]); e1 = __float2bfloat16(pa[3]);
                phi[1] = ((uint32_t)__bfloat16_as_ushort(e1) << 16) | __bfloat16_as_ushort(e0);
                plo[1] = pack_bf16x2(pa[2] - __bfloat162float(e0), pa[3] - __bfloat162float(e1));
                e0 = __float2bfloat16(pb[0]); e1 = __float2bfloat16(pb[1]);
                phi[2] = ((uint32_t)__bfloat16_as_ushort(e1) << 16) | __bfloat16_as_ushort(e0);
                plo[2] = pack_bf16x2(pb[0] - __bfloat162float(e0), pb[1] - __bfloat162float(e1));
                e0 = __float2bfloat16(pb[2]); e1 = __float2bfloat16(pb[3]);
                phi[3] = ((uint32_t)__bfloat16_as_ushort(e1) << 16) | __bfloat16_as_ushort(e0);
                plo[3] = pack_bf16x2(pb[2] - __bfloat162float(e0), pb[3] - __bfloat162float(e1));
            }
#pragma unroll
            for (int ntp = 0; ntp < 8; ntp++) {
                uint32_t vd = ((kt * 16 + vt_kv) * FB_LDH + ntp * 16 + vt_dh) * 2;
                uint32_t vh0, vh1, vh2, vh3, vl0, vl1, vl2, vl3;
                ldsm_x4_t(vh0, vh1, vh2, vh3, sVHI + vd);
                ldsm_x4_t(vl0, vl1, vl2, vl3, sVLO + vd);
                mma16816b(oacc[2*ntp],   phi, vh0, vh1);
                mma16816b(oacc[2*ntp],   phi, vl0, vl1);
                mma16816b(oacc[2*ntp],   plo, vh0, vh1);
                mma16816b(oacc[2*ntp+1], phi, vh2, vh3);
                mma16816b(oacc[2*ntp+1], phi, vl2, vl3);
                mma16816b(oacc[2*ntp+1], plo, vh2, vh3);
            }
        }
        __syncthreads();
    }

    // ---- finalize ----------------------------------------------------------
    const float inv_a = 1.f / l_a;
    const float inv_b = 1.f / l_b;
    const int ta = it * 128 + wq * 16 + (lane >> 2);
    const int tb = ta + 8;
    float* opa = g_att + ((size_t)b * Tt + ta) * Cc + h * Dd;
    float* opb = g_att + ((size_t)b * Tt + tb) * Cc + h * Dd;
#pragma unroll
    for (int nt = 0; nt < 16; nt++) {
        const int d = nt * 8 + (lane & 3) * 2;
        *(float2*)(opa + d) = make_float2(oacc[nt][0] * inv_a, oacc[nt][1] * inv_a);
        *(float2*)(opb + d) = make_float2(oacc[nt][2] * inv_b, oacc[nt][3] * inv_b);
    }
}

// ---------------- launch ----------------------------------------------------
extern "C" void kernel_launch(void* const* d_in, const int* in_sizes, int n_in,
                              void* d_out, int out_size) {
    const float* x  = (const float*)d_in[0];
    const float* Wq = (const float*)d_in[1];
    const float* Wk = (const float*)d_in[2];
    const float* Wv = (const float*)d_in[3];
    const float* Wo = (const float*)d_in[4];
    float* out = (float*)d_out;

    float *pq, *pk, *pv, *patt;
    cudaGetSymbolAddress((void**)&pq,   g_q);
    cudaGetSymbolAddress((void**)&pk,   g_k);
    cudaGetSymbolAddress((void**)&pv,   g_v);
    cudaGetSymbolAddress((void**)&patt, g_att);
    __nv_bfloat16 *pqh, *pql, *pkh, *pkl;
    cudaGetSymbolAddress((void**)&pqh, g_qh);
    cudaGetSymbolAddress((void**)&pql, g_ql);
    cudaGetSymbolAddress((void**)&pkh, g_kh);
    cudaGetSymbolAddress((void**)&pkl, g_kl);

    const int M = Bb * Tt;                 // 4096
    const int gemm_smem = 2 * STAGE_B;     // 81920
    cudaFuncSetAttribute(gemm_hmma_kernel<0>,
                         cudaFuncAttributeMaxDynamicSharedMemorySize, gemm_smem);
    cudaFuncSetAttribute(gemm_hmma_kernel<1>,
                         cudaFuncAttributeMaxDynamicSharedMemorySize, gemm_smem);

    // 1. RoPE tables
    rope_tables_kernel<<<(Tt * 64 + 255) / 256, 256>>>();

    // 2. projections (HMMA split-bf16)
    gemm_hmma_kernel<1><<<dim3(Cc / 128, M / 128), 256, gemm_smem>>>(x, Wq, pq, M, Cc, Cc, Hh);
    gemm_hmma_kernel<1><<<dim3((KVh * Dd) / 128, M / 128), 256, gemm_smem>>>(x, Wk, pk, M, KVh * Dd, Cc, KVh);
    gemm_hmma_kernel<1><<<dim3((KVh * Dd) / 128, M / 128), 256, gemm_smem>>>(x, Wv, pv, M, KVh * Dd, Cc, KVh);

    // 3. RoPE + hi/lo split conversions
    const float scale = 0.08838834764831845f;  // 1/sqrt(128)
    rope_split_kernel<<<(Bb * Hh * Tt * 64 + 255) / 256, 256>>>(pq, pqh, pql, Hh, scale);
    rope_split_kernel<<<(Bb * KVh * Tt * 64 + 255) / 256, 256>>>(pk, pkh, pkl, KVh, 1.0f);
    split_v_kernel<<<(Bb * KVh * Tt * Dd + 255) / 256, 256>>>();

    // 4. flash attention (HMMA, pre-converted bf16, double-buffered)
    cudaFuncSetAttribute(flash_hmma2_kernel,
                         cudaFuncAttributeMaxDynamicSharedMemorySize, FB_SMEM);
    flash_hmma2_kernel<<<dim3(Tt / 128, Hh, Bb), 256, FB_SMEM>>>();

    // 5. output projection
    gemm_hmma_kernel<0><<<dim3(Cc / 128, M / 128), 256, gemm_smem>>>(patt, Wo, out, M, Cc, Cc, 0);
}

// round 7
// speedup vs baseline: 3.3766x; 1.0089x over previous
#include <cuda_runtime.h>
#include <cuda_bf16.h>
#include <math.h>
#include <stdint.h>

#define Bb  2
#define Tt  2048
#define Cc  2048
#define Hh  16
#define KVh 4
#define Dd  128
#define REP 4   // Hh / KVh

// ---------------- scratch (device globals; no allocation allowed) ----------
__device__ float g_cos[Tt * 64];
__device__ float g_sin[Tt * 64];
__device__ float g_q[(size_t)Bb * Hh  * Tt * Dd];   // (b,h,t,d) fp32 (pre-rope)
__device__ float g_k[(size_t)Bb * KVh * Tt * Dd];
__device__ float g_v[(size_t)Bb * KVh * Tt * Dd];
__device__ float g_att[(size_t)Bb * Tt * Cc];       // (b*t, h*d) row-major

// bf16 hi/lo pre-converted operands for flash attention
__device__ __nv_bfloat16 g_qh[(size_t)Bb * Hh  * Tt * Dd];
__device__ __nv_bfloat16 g_ql[(size_t)Bb * Hh  * Tt * Dd];
__device__ __nv_bfloat16 g_kh[(size_t)Bb * KVh * Tt * Dd];
__device__ __nv_bfloat16 g_kl[(size_t)Bb * KVh * Tt * Dd];
__device__ __nv_bfloat16 g_vh[(size_t)Bb * KVh * Tt * Dd];
__device__ __nv_bfloat16 g_vl[(size_t)Bb * KVh * Tt * Dd];

// ---------------- RoPE tables ----------------------------------------------
__global__ void rope_tables_kernel() {
    int idx = blockIdx.x * blockDim.x + threadIdx.x;
    if (idx >= Tt * 64) return;
    int t = idx / 64, i = idx % 64;
    double inv = pow(10000.0, -(double)(2 * i) / 128.0);
    double ang = (double)t * inv;
    g_cos[idx] = (float)cos(ang);
    g_sin[idx] = (float)sin(ang);
}

// ======================= helpers ===========================================
__device__ __forceinline__ uint32_t smem_u32_(const void* p) {
    uint32_t a;
    asm("{ .reg .u64 t; cvta.to.shared.u64 t, %1; cvt.u32.u64 %0, t; }"
        : "=r"(a) : "l"(p));
    return a;
}
__device__ __forceinline__ uint32_t pack_bf16x2(float lo, float hi) {
    uint32_t r;
    asm("cvt.rn.bf16x2.f32 %0, %1, %2;" : "=r"(r) : "f"(hi), "f"(lo));
    return r;
}
__device__ __forceinline__ void split4(float4 v, uint32_t* h2, uint32_t* l2) {
    __nv_bfloat16 e0 = __float2bfloat16(v.x), e1 = __float2bfloat16(v.y);
    __nv_bfloat16 e2 = __float2bfloat16(v.z), e3 = __float2bfloat16(v.w);
    h2[0] = ((uint32_t)__bfloat16_as_ushort(e1) << 16) | __bfloat16_as_ushort(e0);
    h2[1] = ((uint32_t)__bfloat16_as_ushort(e3) << 16) | __bfloat16_as_ushort(e2);
    l2[0] = pack_bf16x2(v.x - __bfloat162float(e0), v.y - __bfloat162float(e1));
    l2[1] = pack_bf16x2(v.z - __bfloat162float(e2), v.w - __bfloat162float(e3));
}

__device__ __forceinline__ void mma16816(float* c, const uint32_t* a, const uint32_t* b) {
    asm volatile(
        "mma.sync.aligned.m16n8k16.row.col.f32.bf16.bf16.f32 "
        "{%0,%1,%2,%3}, {%4,%5,%6,%7}, {%8,%9}, {%0,%1,%2,%3};"
        : "+f"(c[0]), "+f"(c[1]), "+f"(c[2]), "+f"(c[3])
        : "r"(a[0]), "r"(a[1]), "r"(a[2]), "r"(a[3]), "r"(b[0]), "r"(b[1]));
}
__device__ __forceinline__ void mma16816b(float* c, const uint32_t* a,
                                          uint32_t b0, uint32_t b1) {
    asm volatile(
        "mma.sync.aligned.m16n8k16.row.col.f32.bf16.bf16.f32 "
        "{%0,%1,%2,%3}, {%4,%5,%6,%7}, {%8,%9}, {%0,%1,%2,%3};"
        : "+f"(c[0]), "+f"(c[1]), "+f"(c[2]), "+f"(c[3])
        : "r"(a[0]), "r"(a[1]), "r"(a[2]), "r"(a[3]), "r"(b0), "r"(b1));
}
__device__ __forceinline__ void ldsm_x4(uint32_t& r0, uint32_t& r1, uint32_t& r2,
                                        uint32_t& r3, uint32_t addr) {
    asm volatile("ldmatrix.sync.aligned.m8n8.x4.shared.b16 {%0,%1,%2,%3}, [%4];"
                 : "=r"(r0), "=r"(r1), "=r"(r2), "=r"(r3) : "r"(addr));
}
__device__ __forceinline__ void ldsm_x4_t(uint32_t& r0, uint32_t& r1, uint32_t& r2,
                                          uint32_t& r3, uint32_t addr) {
    asm volatile("ldmatrix.sync.aligned.m8n8.x4.trans.shared.b16 {%0,%1,%2,%3}, [%4];"
                 : "=r"(r0), "=r"(r1), "=r"(r2), "=r"(r3) : "r"(addr));
}
__device__ __forceinline__ void ldsm_x2(uint32_t& r0, uint32_t& r1, uint32_t addr) {
    asm volatile("ldmatrix.sync.aligned.m8n8.x2.shared.b16 {%0,%1}, [%2];"
                 : "=r"(r0), "=r"(r1) : "r"(addr));
}
__device__ __forceinline__ void cp16(uint32_t dst, const void* src) {
    asm volatile("cp.async.cg.shared.global [%0], [%1], 16;" :: "r"(dst), "l"(src));
}
#define CP_COMMIT() asm volatile("cp.async.commit_group;" ::: "memory")
#define CP_WAIT(n)  asm volatile("cp.async.wait_group %0;" :: "n"(n) : "memory")

// ---------------- RoPE + split conversion -----------------------------------
__global__ void rope_split_kernel(const float* __restrict__ src,
                                  __nv_bfloat16* __restrict__ dh,
                                  __nv_bfloat16* __restrict__ dl,
                                  int nheads, float scale) {
    int idx = blockIdx.x * blockDim.x + threadIdx.x;
    int total = Bb * nheads * Tt * 64;
    if (idx >= total) return;
    int d  = idx & 63;
    int t  = (idx >> 6) & (Tt - 1);
    int bh = idx / (64 * Tt);
    float c = g_cos[t * 64 + d];
    float s = g_sin[t * 64 + d];
    size_t base = ((size_t)bh * Tt + t) * Dd;
    float x1 = src[base + d], x2 = src[base + d + 64];
    float y1 = (x1 * c - x2 * s) * scale;
    float y2 = (x2 * c + x1 * s) * scale;
    __nv_bfloat16 h1 = __float2bfloat16(y1);
    __nv_bfloat16 h2 = __float2bfloat16(y2);
    dh[base + d]      = h1;
    dh[base + d + 64] = h2;
    dl[base + d]      = __float2bfloat16(y1 - __bfloat162float(h1));
    dl[base + d + 64] = __float2bfloat16(y2 - __bfloat162float(h2));
}

__global__ void split_v_kernel() {
    int idx = blockIdx.x * blockDim.x + threadIdx.x;
    int total = Bb * KVh * Tt * Dd;
    if (idx >= total) return;
    float y = g_v[idx];
    __nv_bfloat16 h = __float2bfloat16(y);
    g_vh[idx] = h;
    g_vl[idx] = __float2bfloat16(y - __bfloat162float(h));
}

// ======================= HMMA split-bf16 GEMM ===============================
#define BK      32
#define LDH     40
#define TILE_B  (128 * LDH * 2)
#define STAGE_B (4 * TILE_B)

template <int MODE>
__global__ void __launch_bounds__(256, 1)
gemm_hmma_kernel(const float* __restrict__ A, const float* __restrict__ Bm,
                 float* __restrict__ Cout, int M, int N, int K, int nh)
{
    extern __shared__ char smem[];
    const uint32_t sb = smem_u32_(smem);

    const int tid  = threadIdx.x;
    const int wid  = tid >> 5;
    const int lane = tid & 31;
    const int wr   = wid >> 2;
    const int wc   = wid & 3;
    const int m0   = blockIdx.y * 128;
    const int n0   = blockIdx.x * 128;

    const int srow = tid >> 1;
    const int sseg = tid & 1;
    const float* aptr = A  + (size_t)(m0 + srow) * K + sseg * 16;
    const float* bptr = Bm + (size_t)(n0 + srow) * K + sseg * 16;

    float acc[4][4][4];
#pragma unroll
    for (int i = 0; i < 4; i++)
#pragma unroll
        for (int j = 0; j < 4; j++)
#pragma unroll
            for (int q = 0; q < 4; q++) acc[i][j][q] = 0.f;

    const int NC = K / BK;

    auto store_chunk = [&](const float4* ga, const float4* gb, int stage) {
        uint32_t hA[8], lA[8], hB[8], lB[8];
#pragma unroll
        for (int g = 0; g < 4; g++) split4(ga[g], hA + 2*g, lA + 2*g);
#pragma unroll
        for (int g = 0; g < 4; g++) split4(gb[g], hB + 2*g, lB + 2*g);
        char* st = smem + stage * STAGE_B;
        uint32_t off = (uint32_t)(srow * LDH + sseg * 16) * 2;
        *(uint4*)(st + 0*TILE_B + off)      = *(uint4*)&hA[0];
        *(uint4*)(st + 0*TILE_B + off + 16) = *(uint4*)&hA[4];
        *(uint4*)(st + 1*TILE_B + off)      = *(uint4*)&lA[0];
        *(uint4*)(st + 1*TILE_B + off + 16) = *(uint4*)&lA[4];
        *(uint4*)(st + 2*TILE_B + off)      = *(uint4*)&hB[0];
        *(uint4*)(st + 2*TILE_B + off + 16) = *(uint4*)&hB[4];
        *(uint4*)(st + 3*TILE_B + off)      = *(uint4*)&lB[0];
        *(uint4*)(st + 3*TILE_B + off + 16) = *(uint4*)&lB[4];
    };

    float4 ga[4], gb[4];
#pragma unroll
    for (int g = 0; g < 4; g++) {
        ga[g] = *(const float4*)(aptr + g * 4);
        gb[g] = *(const float4*)(bptr + g * 4);
    }
    store_chunk(ga, gb, 0);
    __syncthreads();

    const uint32_t a_row = wr * 64 + (lane & 15);
    const uint32_t a_kh  = (lane >> 4) * 8;
    const uint32_t b_row = wc * 32 + (lane & 7);
    const uint32_t b_kh  = ((lane >> 3) & 1) * 8;

    for (int i = 0; i < NC; i++) {
        const int s = i & 1;
        if (i + 1 < NC) {
            const int kk = (i + 1) * BK;
#pragma unroll
            for (int g = 0; g < 4; g++) {
                ga[g] = *(const float4*)(aptr + kk + g * 4);
                gb[g] = *(const float4*)(bptr + kk + g * 4);
            }
        }

        const uint32_t stb = sb + s * STAGE_B;
#pragma unroll
        for (int kstep = 0; kstep < 2; kstep++) {
            const uint32_t kof = kstep * 16;
            uint32_t ahi[4][4], alo[4][4], bhi[4][2], blo[4][2];
#pragma unroll
            for (int mt = 0; mt < 4; mt++) {
                uint32_t ad = stb + ((a_row + mt * 16) * LDH + kof + a_kh) * 2;
                ldsm_x4(ahi[mt][0], ahi[mt][1], ahi[mt][2], ahi[mt][3], ad + 0 * TILE_B);
                ldsm_x4(alo[mt][0], alo[mt][1], alo[mt][2], alo[mt][3], ad + 1 * TILE_B);
            }
#pragma unroll
            for (int nt = 0; nt < 4; nt++) {
                uint32_t bd = stb + ((b_row + nt * 8) * LDH + kof + b_kh) * 2;
                ldsm_x2(bhi[nt][0], bhi[nt][1], bd + 2 * TILE_B);
                ldsm_x2(blo[nt][0], blo[nt][1], bd + 3 * TILE_B);
            }
#pragma unroll
            for (int mt = 0; mt < 4; mt++)
#pragma unroll
                for (int nt = 0; nt < 4; nt++) {
                    mma16816(acc[mt][nt], ahi[mt], bhi[nt]);
                    mma16816(acc[mt][nt], ahi[mt], blo[nt]);
                    mma16816(acc[mt][nt], alo[mt], bhi[nt]);
                }
        }
        __syncthreads();
        if (i + 1 < NC) {
            store_chunk(ga, gb, s ^ 1);
            __syncthreads();
        }
    }

#pragma unroll
    for (int mt = 0; mt < 4; mt++) {
        const int r0 = m0 + wr * 64 + mt * 16 + (lane >> 2);
        const int r1 = r0 + 8;
#pragma unroll
        for (int nt = 0; nt < 4; nt++) {
            const int c = n0 + wc * 32 + nt * 8 + (lane & 3) * 2;
            if (MODE == 0) {
                *(float2*)(Cout + (size_t)r0 * N + c) = make_float2(acc[mt][nt][0], acc[mt][nt][1]);
                *(float2*)(Cout + (size_t)r1 * N + c) = make_float2(acc[mt][nt][2], acc[mt][nt][3]);
            } else {
                const int h = c >> 7, d = c & 127;
                const int b0_ = r0 / Tt, t0_ = r0 & (Tt - 1);
                const int b1_ = r1 / Tt, t1_ = r1 & (Tt - 1);
                *(float2*)(Cout + (((size_t)b0_ * nh + h) * Tt + t0_) * Dd + d) =
                    make_float2(acc[mt][nt][0], acc[mt][nt][1]);
                *(float2*)(Cout + (((size_t)b1_ * nh + h) * Tt + t1_) * Dd + d) =
                    make_float2(acc[mt][nt][2], acc[mt][nt][3]);
            }
        }
    }
}

// ================= HMMA flash attention, pre-converted bf16 =================
// Block: 128 q-rows, 8 warps. KV tile 64. Q stays in SMEM (fragments reloaded
// per k-step) to keep register count spill-free. Softmax in base-2 domain
// (log2e folded into the Q pre-scale).

#define FB_LDH  136                    // halves per smem row (128 + 8 pad)
#define FB_ROW  (FB_LDH * 2)           // 272 bytes
#define FB_MAT  (64 * FB_ROW)          // 17408
#define FB_STG  (4 * FB_MAT)           // 69632 (Khi,Klo,Vhi,Vlo)
#define FB_QOFF (2 * FB_STG)
#define FB_SMEM (FB_QOFF + 2 * 128 * FB_ROW)   // 208896

__global__ void __launch_bounds__(256, 1)
flash_hmma2_kernel() {
    extern __shared__ char smem[];
    const uint32_t sb = smem_u32_(smem);

    const int it = (Tt / 128 - 1) - blockIdx.x;   // heavy blocks first
    const int h  = blockIdx.y;
    const int b  = blockIdx.z;
    const int kvh = h / REP;

    const __nv_bfloat16* qh = g_qh + (((size_t)b * Hh + h) * Tt + it * 128) * Dd;
    const __nv_bfloat16* ql = g_ql + (((size_t)b * Hh + h) * Tt + it * 128) * Dd;
    const __nv_bfloat16* kh = g_kh + ((size_t)b * KVh + kvh) * Tt * Dd;
    const __nv_bfloat16* kl = g_kl + ((size_t)b * KVh + kvh) * Tt * Dd;
    const __nv_bfloat16* vh = g_vh + ((size_t)b * KVh + kvh) * Tt * Dd;
    const __nv_bfloat16* vl = g_vl + ((size_t)b * KVh + kvh) * Tt * Dd;

    const int tid  = threadIdx.x;
    const int wq   = tid >> 5;
    const int lane = tid & 31;

    auto load_tile = [&](int jt, int stg) {
        const uint32_t db = sb + stg * FB_STG;
        const size_t gb0 = (size_t)jt * 64 * Dd;
#pragma unroll
        for (int c = tid; c < 1024; c += 256) {
            const uint32_t d = db + (c >> 4) * FB_ROW + (c & 15) * 16;
            const size_t  o = gb0 + (c >> 4) * Dd + (c & 15) * 8;
            cp16(d + 0 * FB_MAT, kh + o);
            cp16(d + 1 * FB_MAT, kl + o);
            cp16(d + 2 * FB_MAT, vh + o);
            cp16(d + 3 * FB_MAT, vl + o);
        }
    };

#pragma unroll
    for (int c = tid; c < 2048; c += 256) {
        const uint32_t d = sb + FB_QOFF + (c >> 4) * FB_ROW + (c & 15) * 16;
        const size_t  o = (size_t)(c >> 4) * Dd + (c & 15) * 8;
        cp16(d, qh + o);
        cp16(d + 128 * FB_ROW, ql + o);
    }
    load_tile(0, 0);
    CP_COMMIT();
    CP_WAIT(0);
    __syncthreads();

    float m_a = -1e30f, m_b = -1e30f, l_a = 0.f, l_b = 0.f;
    float oacc[16][4];
#pragma unroll
    for (int nt = 0; nt < 16; nt++)
#pragma unroll
        for (int q = 0; q < 4; q++) oacc[nt][q] = 0.f;

    const uint32_t kb_row = (lane & 7) + ((lane >> 4) * 8);
    const uint32_t kb_kh  = ((lane >> 3) & 1) * 8;
    const uint32_t vt_kv  = lane & 15;
    const uint32_t vt_dh  = (lane >> 4) * 8;
    // Q fragment lane addressing (reloaded per k-step)
    const uint32_t qa = sb + FB_QOFF + (wq * 16 + (lane & 15)) * FB_ROW + ((lane >> 4) * 8) * 2;

    const int jmax = 2 * it + 1;

    for (int jt = 0; jt <= jmax; jt++) {
        const int s = jt & 1;
        if (jt + 1 <= jmax) {
            load_tile(jt + 1, s ^ 1);
            CP_COMMIT();
            CP_WAIT(1);
        } else {
            CP_WAIT(0);
        }
        __syncthreads();

        const uint32_t sKHI = sb + s * FB_STG;
        const uint32_t sKLO = sKHI + FB_MAT;
        const uint32_t sVHI = sKHI + 2 * FB_MAT;
        const uint32_t sVLO = sKHI + 3 * FB_MAT;

        // ---- S = Q K^T (3-pass), Q frags reloaded from smem per k-step ----
        float sacc[8][4];
#pragma unroll
        for (int nt = 0; nt < 8; nt++)
#pragma unroll
            for (int q = 0; q < 4; q++) sacc[nt][q] = 0.f;

#pragma unroll
        for (int ks = 0; ks < 8; ks++) {
            uint32_t qhi[4], qlo[4];
            {
                uint32_t ad = qa + ks * 32;   // 16 halves per k-step
                ldsm_x4(qhi[0], qhi[1], qhi[2], qhi[3], ad);
                ldsm_x4(qlo[0], qlo[1], qlo[2], qlo[3], ad + 128 * FB_ROW);
            }
#pragma unroll
            for (int ntp = 0; ntp < 4; ntp++) {
                uint32_t bd = ((ntp * 16 + kb_row) * FB_LDH + ks * 16 + kb_kh) * 2;
                uint32_t kh0, kh1, kh2, kh3, kl0, kl1, kl2, kl3;
                ldsm_x4(kh0, kh1, kh2, kh3, sKHI + bd);
                ldsm_x4(kl0, kl1, kl2, kl3, sKLO + bd);
                mma16816b(sacc[2*ntp],   qhi, kh0, kh1);
                mma16816b(sacc[2*ntp],   qhi, kl0, kl1);
                mma16816b(sacc[2*ntp],   qlo, kh0, kh1);
                mma16816b(sacc[2*ntp+1], qhi, kh2, kh3);
                mma16816b(sacc[2*ntp+1], qhi, kl2, kl3);
                mma16816b(sacc[2*ntp+1], qlo, kh2, kh3);
            }
        }

        // ---- causal mask ---------------------------------------------------
        if (jt >= 2 * it) {
            const int ra = it * 128 + wq * 16 + (lane >> 2);
            const int cb = jt * 64 + (lane & 3) * 2;
#pragma unroll
            for (int nt = 0; nt < 8; nt++) {
                const int c0 = cb + nt * 8;
                if (c0 > ra)         sacc[nt][0] = -1e30f;
                if (c0 + 1 > ra)     sacc[nt][1] = -1e30f;
                if (c0 > ra + 8)     sacc[nt][2] = -1e30f;
                if (c0 + 1 > ra + 8) sacc[nt][3] = -1e30f;
            }
        }

        // ---- online softmax (base-2 domain) -------------------------------
        float mx_a = -1e30f, mx_b = -1e30f;
#pragma unroll
        for (int nt = 0; nt < 8; nt++) {
            mx_a = fmaxf(mx_a, fmaxf(sacc[nt][0], sacc[nt][1]));
            mx_b = fmaxf(mx_b, fmaxf(sacc[nt][2], sacc[nt][3]));
        }
        mx_a = fmaxf(mx_a, __shfl_xor_sync(0xffffffffu, mx_a, 1));
        mx_a = fmaxf(mx_a, __shfl_xor_sync(0xffffffffu, mx_a, 2));
        mx_b = fmaxf(mx_b, __shfl_xor_sync(0xffffffffu, mx_b, 1));
        mx_b = fmaxf(mx_b, __shfl_xor_sync(0xffffffffu, mx_b, 2));

        const float mn_a = fmaxf(m_a, mx_a);
        const float mn_b = fmaxf(m_b, mx_b);
        const float al_a = exp2f(m_a - mn_a);
        const float al_b = exp2f(m_b - mn_b);
        m_a = mn_a; m_b = mn_b;

        float ls_a = 0.f, ls_b = 0.f;
#pragma unroll
        for (int nt = 0; nt < 8; nt++) {
            float p0 = exp2f(sacc[nt][0] - mn_a);
            float p1 = exp2f(sacc[nt][1] - mn_a);
            float p2 = exp2f(sacc[nt][2] - mn_b);
            float p3 = exp2f(sacc[nt][3] - mn_b);
            sacc[nt][0] = p0; sacc[nt][1] = p1; sacc[nt][2] = p2; sacc[nt][3] = p3;
            ls_a += p0 + p1; ls_b += p2 + p3;
        }
        ls_a += __shfl_xor_sync(0xffffffffu, ls_a, 1);
        ls_a += __shfl_xor_sync(0xffffffffu, ls_a, 2);
        ls_b += __shfl_xor_sync(0xffffffffu, ls_b, 1);
        ls_b += __shfl_xor_sync(0xffffffffu, ls_b, 2);
        l_a = l_a * al_a + ls_a;
        l_b = l_b * al_b + ls_b;

#pragma unroll
        for (int nt = 0; nt < 16; nt++) {
            oacc[nt][0] *= al_a; oacc[nt][1] *= al_a;
            oacc[nt][2] *= al_b; oacc[nt][3] *= al_b;
        }

        // ---- O += P V (3-pass) --------------------------------------------
#pragma unroll
        for (int kt = 0; kt < 4; kt++) {
            uint32_t phi[4], plo[4];
            {
                float* pa = sacc[2*kt];
                float* pb = sacc[2*kt + 1];
                __nv_bfloat16 e0, e1;
                e0 = __float2bfloat16(pa[0]); e1 = __float2bfloat16(pa[1]);
                phi[0] = ((uint32_t)__bfloat16_as_ushort(e1) << 16) | __bfloat16_as_ushort(e0);
                plo[0] = pack_bf16x2(pa[0] - __bfloat162float(e0), pa[1] - __bfloat162float(e1));
                e0 = __float2bfloat16(pa[2]); e1 = __float2bfloat16(pa[3]);
                phi[1] = ((uint32_t)__bfloat16_as_ushort(e1) << 16) | __bfloat16_as_ushort(e0);
                plo[1] = pack_bf16x2(pa[2] - __bfloat162float(e0), pa[3] - __bfloat162float(e1));
                e0 = __float2bfloat16(pb[0]); e1 = __float2bfloat16(pb[1]);
                phi[2] = ((uint32_t)__bfloat16_as_ushort(e1) << 16) | __bfloat16_as_ushort(e0);
                plo[2] = pack_bf16x2(pb[0] - __bfloat162float(e0), pb[1] - __bfloat162float(e1));
                e0 = __float2bfloat16(pb[2]); e1 = __float2bfloat16(pb[3]);
                phi[3] = ((uint32_t)__bfloat16_as_ushort(e1) << 16) | __bfloat16_as_ushort(e0);
                plo[3] = pack_bf16x2(pb[2] - __bfloat162float(e0), pb[3] - __bfloat162float(e1));
            }
#pragma unroll
            for (int ntp = 0; ntp < 8; ntp++) {
                uint32_t vd = ((kt * 16 + vt_kv) * FB_LDH + ntp * 16 + vt_dh) * 2;
                uint32_t vh0, vh1, vh2, vh3, vl0, vl1, vl2, vl3;
                ldsm_x4_t(vh0, vh1, vh2, vh3, sVHI + vd);
                ldsm_x4_t(vl0, vl1, vl2, vl3, sVLO + vd);
                mma16816b(oacc[2*ntp],   phi, vh0, vh1);
                mma16816b(oacc[2*ntp],   phi, vl0, vl1);
                mma16816b(oacc[2*ntp],   plo, vh0, vh1);
                mma16816b(oacc[2*ntp+1], phi, vh2, vh3);
                mma16816b(oacc[2*ntp+1], phi, vl2, vl3);
                mma16816b(oacc[2*ntp+1], plo, vh2, vh3);
            }
        }
        __syncthreads();
    }

    // ---- finalize ----------------------------------------------------------
    const float inv_a = 1.f / l_a;
    const float inv_b = 1.f / l_b;
    const int ta = it * 128 + wq * 16 + (lane >> 2);
    const int tb = ta + 8;
    float* opa = g_att + ((size_t)b * Tt + ta) * Cc + h * Dd;
    float* opb = g_att + ((size_t)b * Tt + tb) * Cc + h * Dd;
#pragma unroll
    for (int nt = 0; nt < 16; nt++) {
        const int d = nt * 8 + (lane & 3) * 2;
        *(float2*)(opa + d) = make_float2(oacc[nt][0] * inv_a, oacc[nt][1] * inv_a);
        *(float2*)(opb + d) = make_float2(oacc[nt][2] * inv_b, oacc[nt][3] * inv_b);
    }
}

// ---------------- launch ----------------------------------------------------
extern "C" void kernel_launch(void* const* d_in, const int* in_sizes, int n_in,
                              void* d_out, int out_size) {
    const float* x  = (const float*)d_in[0];
    const float* Wq = (const float*)d_in[1];
    const float* Wk = (const float*)d_in[2];
    const float* Wv = (const float*)d_in[3];
    const float* Wo = (const float*)d_in[4];
    float* out = (float*)d_out;

    float *pq, *pk, *pv, *patt;
    cudaGetSymbolAddress((void**)&pq,   g_q);
    cudaGetSymbolAddress((void**)&pk,   g_k);
    cudaGetSymbolAddress((void**)&pv,   g_v);
    cudaGetSymbolAddress((void**)&patt, g_att);
    __nv_bfloat16 *pqh, *pql, *pkh, *pkl;
    cudaGetSymbolAddress((void**)&pqh, g_qh);
    cudaGetSymbolAddress((void**)&pql, g_ql);
    cudaGetSymbolAddress((void**)&pkh, g_kh);
    cudaGetSymbolAddress((void**)&pkl, g_kl);

    const int M = Bb * Tt;                 // 4096
    const int gemm_smem = 2 * STAGE_B;     // 81920
    cudaFuncSetAttribute(gemm_hmma_kernel<0>,
                         cudaFuncAttributeMaxDynamicSharedMemorySize, gemm_smem);
    cudaFuncSetAttribute(gemm_hmma_kernel<1>,
                         cudaFuncAttributeMaxDynamicSharedMemorySize, gemm_smem);

    // 1. RoPE tables
    rope_tables_kernel<<<(Tt * 64 + 255) / 256, 256>>>();

    // 2. projections (HMMA split-bf16)
    gemm_hmma_kernel<1><<<dim3(Cc / 128, M / 128), 256, gemm_smem>>>(x, Wq, pq, M, Cc, Cc, Hh);
    gemm_hmma_kernel<1><<<dim3((KVh * Dd) / 128, M / 128), 256, gemm_smem>>>(x, Wk, pk, M, KVh * Dd, Cc, KVh);
    gemm_hmma_kernel<1><<<dim3((KVh * Dd) / 128, M / 128), 256, gemm_smem>>>(x, Wv, pv, M, KVh * Dd, Cc, KVh);

    // 3. RoPE + hi/lo split conversions. Q pre-scale folds 1/sqrt(D) AND
    //    log2(e) so the softmax runs in the base-2 domain.
    const float qscale = 0.08838834764831845f * 1.4426950408889634f;
    rope_split_kernel<<<(Bb * Hh * Tt * 64 + 255) / 256, 256>>>(pq, pqh, pql, Hh, qscale);
    rope_split_kernel<<<(Bb * KVh * Tt * 64 + 255) / 256, 256>>>(pk, pkh, pkl, KVh, 1.0f);
    split_v_kernel<<<(Bb * KVh * Tt * Dd + 255) / 256, 256>>>();

    // 4. flash attention
    cudaFuncSetAttribute(flash_hmma2_kernel,
                         cudaFuncAttributeMaxDynamicSharedMemorySize, FB_SMEM);
    flash_hmma2_kernel<<<dim3(Tt / 128, Hh, Bb), 256, FB_SMEM>>>();

    // 5. output projection
    gemm_hmma_kernel<0><<<dim3(Cc / 128, M / 128), 256, gemm_smem>>>(patt, Wo, out, M, Cc, Cc, 0);
}